// round 11
// baseline (speedup 1.0000x reference)
#include <cuda_runtime.h>
#include <cuda_fp16.h>
#include <math.h>
#include <stdint.h>

#define B_    8
#define N_    4096
#define CIN_  64
#define COUT_ 128
#define R_    32
#define R3_   32768
#define NG_   8
#define GN_EPS_ 1e-5f

// ---------------- scratch (static device globals; no allocation) -------------
// grid is TRANSPOSED: [b][voxel][ci]  (ci contiguous)
static __device__ float g_grid[B_ * R3_ * CIN_];
static __device__ float g_cnt [B_ * R3_];
static __device__ int   g_vox [B_ * N_];
static __device__ float g_nc  [B_ * N_ * 3];
static __device__ float g_h1  [B_ * COUT_ * R3_];
static __device__ float g_h2  [B_ * COUT_ * R3_];
static __device__ float g_pf  [B_ * COUT_ * N_];
static __device__ float g_mean [B_ * NG_];
static __device__ float g_rstd [B_ * NG_];
static __device__ float g_mean2[B_ * NG_];
static __device__ float g_rstd2[B_ * NG_];
static __device__ float g_sum [B_ * NG_];
static __device__ float g_sum2[B_ * NG_];
// fp16 weights: [tap][ci-chunk32][co 128][ci 32]
static __device__ __half g_w1[27 * 2 * 128 * 32];
static __device__ __half g_w2[27 * 4 * 128 * 32];

// ---------------- mma.sync m16n8k16 fp16 ------------------------------------
#define MMA_F16(dd, a0, a1, a2, a3, b0, b1) \
    asm volatile("mma.sync.aligned.m16n8k16.row.col.f32.f16.f16.f32 " \
        "{%0,%1,%2,%3}, {%4,%5,%6,%7}, {%8,%9}, {%0,%1,%2,%3};" \
        : "+f"((dd)[0]), "+f"((dd)[1]), "+f"((dd)[2]), "+f"((dd)[3]) \
        : "r"(a0), "r"(a1), "r"(a2), "r"(a3), "r"(b0), "r"(b1))

__device__ __forceinline__ void ldsm4(uint32_t* r, uint32_t addr) {
    asm volatile("ldmatrix.sync.aligned.m8n8.x4.shared.b16 {%0,%1,%2,%3}, [%4];"
        : "=r"(r[0]), "=r"(r[1]), "=r"(r[2]), "=r"(r[3]) : "r"(addr));
}
__device__ __forceinline__ uint32_t smem_u32(const void* p) {
    uint32_t a;
    asm("{ .reg .u64 t; cvta.to.shared.u64 t, %1; cvt.u32.u64 %0, t; }" : "=r"(a) : "l"(p));
    return a;
}

// ============================ coords ==========================================
__global__ void coords_kernel(const float* __restrict__ coords,
                              float* __restrict__ nc, int* __restrict__ vox,
                              float* __restrict__ cnt) {
    int b = blockIdx.x, tid = threadIdx.x;
    __shared__ float red[256];
    __shared__ float smean[3];
    __shared__ float sinv;

    float s0 = 0.f, s1 = 0.f, s2 = 0.f;
    for (int n = tid; n < N_; n += 256) {
        const float* c = &coords[(b * N_ + n) * 3];
        s0 += c[0]; s1 += c[1]; s2 += c[2];
    }
    float ss[3] = {s0, s1, s2};
    for (int d = 0; d < 3; d++) {
        red[tid] = ss[d]; __syncthreads();
        for (int st = 128; st > 0; st >>= 1) {
            if (tid < st) red[tid] += red[tid + st];
            __syncthreads();
        }
        if (tid == 0) smean[d] = red[0] * (1.0f / N_);
        __syncthreads();
    }
    float m0 = smean[0], m1 = smean[1], m2 = smean[2];

    float mx = 0.f;
    for (int n = tid; n < N_; n += 256) {
        const float* c = &coords[(b * N_ + n) * 3];
        float dx = c[0] - m0, dy = c[1] - m1, dz = c[2] - m2;
        mx = fmaxf(mx, dx * dx + dy * dy + dz * dz);
    }
    red[tid] = mx; __syncthreads();
    for (int st = 128; st > 0; st >>= 1) {
        if (tid < st) red[tid] = fmaxf(red[tid], red[tid + st]);
        __syncthreads();
    }
    if (tid == 0) sinv = 1.0f / (2.0f * sqrtf(red[0]));
    __syncthreads();
    float inv = sinv;

    for (int n = tid; n < N_; n += 256) {
        const float* c = &coords[(b * N_ + n) * 3];
        float v[3]; int iv[3];
        float cc[3] = {c[0] - m0, c[1] - m1, c[2] - m2};
        #pragma unroll
        for (int d = 0; d < 3; d++) {
            float x = (cc[d] * inv + 0.5f) * (float)R_;
            x = fminf(fmaxf(x, 0.f), (float)(R_ - 1));
            v[d] = x;
            iv[d] = (int)rintf(x);
        }
        nc[(b * N_ + n) * 3 + 0] = v[0];
        nc[(b * N_ + n) * 3 + 1] = v[1];
        nc[(b * N_ + n) * 3 + 2] = v[2];
        int flat = (iv[0] * R_ + iv[1]) * R_ + iv[2];
        vox[b * N_ + n] = flat;
        atomicAdd(&cnt[b * R3_ + flat], 1.0f);
    }
}

// ---------------- weight prep (both convs): fp32 -> fp16 ---------------------
__global__ void wprep2_kernel(const float* __restrict__ w1, const float* __restrict__ w2,
                              __half* __restrict__ o1, __half* __restrict__ o2) {
    int t = blockIdx.x * 256 + threadIdx.x;
    const int N1 = 27 * 128 * CIN_;
    if (t < N1) {
        int ci = t % CIN_;
        int co = (t / CIN_) & 127;
        int tap = t / (CIN_ * 128);
        float v = w1[(co * CIN_ + ci) * 27 + tap];
        int idx = ((tap * (CIN_ >> 5) + (ci >> 5)) * 128 + co) * 32 + (ci & 31);
        o1[idx] = __float2half_rn(v);
    } else {
        t -= N1;
        if (t >= 27 * 128 * COUT_) return;
        int ci = t % COUT_;
        int co = (t / COUT_) & 127;
        int tap = t / (COUT_ * 128);
        float v = w2[(co * COUT_ + ci) * 27 + tap];
        int idx = ((tap * (COUT_ >> 5) + (ci >> 5)) * 128 + co) * 32 + (ci & 31);
        o2[idx] = __float2half_rn(v);
    }
}

// ---------------- scatter (smem transpose -> coalesced atomics) --------------
__global__ void scatter_t_kernel(const float* __restrict__ f,
                                 const int* __restrict__ vox,
                                 float* __restrict__ grid) {
    int b = blockIdx.x >> 6, ng = blockIdx.x & 63;
    int n0 = ng * 64;
    int tid = threadIdx.x;
    __shared__ float buf[64][65];
    #pragma unroll
    for (int k = 0; k < 16; k++) {
        int idx = k * 256 + tid;
        int c = idx >> 6, dn = idx & 63;
        buf[c][dn] = f[((size_t)b * 64 + c) * N_ + n0 + dn];
    }
    __syncthreads();
    #pragma unroll
    for (int k = 0; k < 16; k++) {
        int idx = k * 256 + tid;
        int dn = idx >> 6, c = idx & 63;
        int flat = vox[b * N_ + n0 + dn];
        atomicAdd(&grid[((size_t)b * R3_ + flat) * 64 + c], buf[c][dn]);
    }
}

// ---------------- cleanup (end of run): zero occupied grid cols + cnt --------
__global__ void cleanup_kernel(const int* __restrict__ vox,
                               float* __restrict__ grid, float* __restrict__ cnt) {
    int t = blockIdx.x * 256 + threadIdx.x;   // B*N
    int b = t >> 12;
    int flat = vox[t];
    cnt[b * R3_ + flat] = 0.f;
    float4* g4 = (float4*)&grid[((size_t)b * R3_ + flat) * 64];
    const float4 z = make_float4(0.f, 0.f, 0.f, 0.f);
    #pragma unroll
    for (int k = 0; k < 16; k++) g4[k] = z;
}

// ============================ mma.sync conv3d (fp16) =========================
// CTA: 128 thr = 4 FAT warps. Output tile: [128 co] x [2x2 xy lines x 32 z].
// Warp w: cobase = (w>>1)*64 (m=64), lx = w&1, lines {lx*2, lx*2+1} (n=64).
// Per warp per tap: 8 A-ldsm4 + 8 B-ldsm4 for 64 MMAs (vs 12/32 before).
// SMEM: X [16 line tiles][34 z][40 pad] fp16 at 0 (43,520 B)
//       W double buffer [128][40] fp16 per buf at 43,520 (2 x 10,240 B)
//       flags[16] at 64,000 ; rc[512]/sscale+sshift[64] at 64,064
#define LSTRB   2720
#define W_OFF   43520
#define WBUF    10240
#define FLG_OFF 64000
#define RC_OFF  64064
#define CONV_SMEM 66112

__global__ __launch_bounds__(128, 2)
void conv3d_mma_kernel(const float* __restrict__ in,
                       const __half* __restrict__ wgt,
                       const float* __restrict__ bias,
                       float* __restrict__ out, int Cin,
                       const float* __restrict__ cnt,    // conv1: transposed in + 1/cnt
                       const float* __restrict__ gnm, const float* __restrict__ gnrs,
                       const float* __restrict__ gng, const float* __restrict__ gnb,
                       float* __restrict__ gs, float* __restrict__ gs2) {
    extern __shared__ __align__(16) char smem[];
    __half* X = (__half*)smem;
    int* flags = (int*)(smem + FLG_OFF);
    float* rc = (float*)(smem + RC_OFF);
    float* sscale = (float*)(smem + RC_OFF);
    float* sshift = sscale + 32;
    uint32_t sb = smem_u32(smem);
    uint32_t x_u = sb, w_u = sb + W_OFF;

    int tid = threadIdx.x, wid = tid >> 5, lane = tid & 31;
    int bx = blockIdx.x, b = blockIdx.y;
    int x0 = (bx >> 4) * 2, y0 = (bx & 15) * 2;
    int nch = Cin >> 5;
    int lx = wid & 1;                  // warp's x-line
    int cobase = (wid >> 1) * 64;      // warp's co half
    int g = lane >> 2, t4 = lane & 3;
    bool hc = (cnt != nullptr);

    uint32_t a_off = ((uint32_t)((lane & 7) + ((lane >> 3) & 1) * 8) * 40
                      + (uint32_t)(lane >> 4) * 8) * 2;
    uint32_t b_off = ((uint32_t)((lane & 7) + (lane >> 4) * 8) * 40
                      + (uint32_t)((lane >> 3) & 1) * 8) * 2;

    // W staging: each thread copies one co row (4 uint4 = 32 ci)
    uint32_t wrow = (uint32_t)tid * 80;

    if (tid < 16) flags[tid] = hc ? 0 : 1;
    __syncthreads();
    if (hc) {   // per-column reciprocal counts + nonzero flags (conv1)
        for (int i = tid; i < 512; i += 128) {
            int il = i >> 5, z = i & 31;
            int gx = x0 - 1 + (il >> 2), gy = y0 - 1 + (il & 3);
            float c = 0.f;
            if ((unsigned)gx < 32u && (unsigned)gy < 32u)
                c = cnt[(size_t)b * R3_ + gx * 1024 + gy * 32 + z];
            rc[i] = __frcp_rn(fmaxf(c, 1.f));
            if (c > 0.f) flags[il] = 1;
        }
    }

    float d[4][2][4][4];   // [m-frag][line][n-frag][vals]
    #pragma unroll
    for (int m = 0; m < 4; m++)
        #pragma unroll
        for (int l = 0; l < 2; l++)
            #pragma unroll
            for (int n = 0; n < 4; n++)
                #pragma unroll
                for (int r = 0; r < 4; r++) d[m][l][n][r] = 0.f;

    for (int ch = 0; ch < nch; ch++) {
        int c0 = ch * 32;
        __syncthreads();                 // prev chunk fully consumed
        if (gng) {                       // conv2: per-chunk GN scale/shift
            if (tid < 32) {
                int cc = c0 + tid;
                int gi = b * NG_ + (cc >> 4);
                float sc = gnrs[gi] * gng[cc];
                sscale[tid] = sc;
                sshift[tid] = gnb[cc] - gnm[gi] * sc;
            }
            __syncthreads();
        }
        // zero z-halo rows
        for (int i = tid; i < 1024; i += 128) {
            int ci = i & 31, r2 = (i >> 5) & 1, il = i >> 6;
            X[il * 1360 + (r2 ? 33 : 0) * 40 + ci] = __float2half_rn(0.f);
        }
        if (hc) {
            // conv1: transposed input [b][voxel][64ci]; 16 lines x 32 z x 8 ci-quads
            for (int i = tid; i < 4096; i += 128) {
                int c4 = i & 7;
                int z  = (i >> 3) & 31;
                int il = i >> 8;
                int gx = x0 - 1 + (il >> 2), gy = y0 - 1 + (il & 3);
                float4 v = make_float4(0.f, 0.f, 0.f, 0.f);
                if ((unsigned)gx < 32u && (unsigned)gy < 32u)
                    v = *(const float4*)&in[((size_t)b * R3_ + gx * 1024 + gy * 32 + z) * 64 + c0 + c4 * 4];
                float r = rc[il * 32 + z];
                int base = il * 1360 + (z + 1) * 40 + c4 * 4;
                *(__half2*)&X[base]     = __floats2half2_rn(v.x * r, v.y * r);
                *(__half2*)&X[base + 2] = __floats2half2_rn(v.z * r, v.w * r);
            }
        } else {
            // conv2: [b][c][voxel] input with fused GN+swish
            for (int i = tid; i < 4096; i += 128) {
                int zq = i & 7, ci = (i >> 3) & 31, il = i >> 8;
                int gx = x0 - 1 + (il >> 2), gy = y0 - 1 + (il & 3);
                float4 v = make_float4(0.f, 0.f, 0.f, 0.f);
                if ((unsigned)gx < 32u && (unsigned)gy < 32u)
                    v = *(const float4*)&in[(((size_t)(b * Cin + c0 + ci) * 32 + gx) * 32 + gy) * 32 + zq * 4];
                float sc = sscale[ci], sh = sshift[ci];
                int base = il * 1360 + (zq * 4 + 1) * 40 + ci;
                #pragma unroll
                for (int j = 0; j < 4; j++) {
                    float y = (&v.x)[j] * sc + sh;
                    y = y / (1.0f + expf(-y));
                    X[base + j * 40] = __float2half_rn(y);
                }
            }
        }
        {   // stage W[tap=0] into buf 0 (thread = one co row)
            const uint4* sh4 = (const uint4*)(wgt + (size_t)(0 * nch + ch) * 4096);
            #pragma unroll
            for (int q = 0; q < 4; q++)
                *(uint4*)(smem + W_OFF + wrow + q * 16) = sh4[tid * 4 + q];
        }
        __syncthreads();

        for (int tap = 0; tap < 27; tap++) {
            int buf = tap & 1;
            uint4 nh[4];
            bool pre = (tap < 26);
            if (pre) {   // register-prefetch next tap's W (overlaps MMAs)
                const uint4* sh4 = (const uint4*)(wgt + (size_t)((tap + 1) * nch + ch) * 4096);
                #pragma unroll
                for (int q = 0; q < 4; q++) nh[q] = sh4[tid * 4 + q];
            }

            int dz = tap % 3, dyy = (tap / 3) % 3, dxx = tap / 9;
            int il0 = (lx + dxx) * 4 + dyy;            // lines il0, il0+1
            int f0 = flags[il0], f1 = flags[il0 + 1];
            if (f0 | f1) {
                uint32_t wb = w_u + (uint32_t)buf * WBUF + (uint32_t)cobase * 80;
                #pragma unroll
                for (int k = 0; k < 2; k++) {
                    uint32_t Af[4][4];
                    #pragma unroll
                    for (int m = 0; m < 4; m++)
                        ldsm4(Af[m], wb + (uint32_t)m * 1280 + (uint32_t)k * 32 + a_off);
                    #pragma unroll
                    for (int l = 0; l < 2; l++) {
                        if (l == 0 ? f0 : f1) {
                            uint32_t xb = x_u + (uint32_t)(il0 + l) * LSTRB + (uint32_t)dz * 80;
                            uint32_t Bf[8];
                            ldsm4(&Bf[0], xb + (uint32_t)k * 32 + b_off);
                            ldsm4(&Bf[4], xb + 1280 + (uint32_t)k * 32 + b_off);
                            #pragma unroll
                            for (int m = 0; m < 4; m++)
                                #pragma unroll
                                for (int n = 0; n < 4; n++)
                                    MMA_F16(d[m][l][n], Af[m][0], Af[m][1], Af[m][2], Af[m][3],
                                            Bf[n * 2], Bf[n * 2 + 1]);
                        }
                    }
                }
            }

            if (pre) {
                char* dst = smem + W_OFF + (buf ^ 1) * WBUF;
                #pragma unroll
                for (int q = 0; q < 4; q++)
                    *(uint4*)(dst + wrow + q * 16) = nh[q];
            }
            __syncthreads();
        }
    }

    // epilogue: write out + fused GroupNorm partial stats
    #pragma unroll
    for (int m = 0; m < 4; m++) {
        int co = cobase + m * 16 + g;
        float bv0 = bias[co], bv1 = bias[co + 8];
        float s = 0.f, s2 = 0.f;
        #pragma unroll
        for (int l = 0; l < 2; l++) {
            int ox = x0 + lx, oy = y0 + l;
            float* p0 = out + ((size_t)(b * COUT_ + co)) * R3_ + ox * 1024 + oy * 32;
            float* p1 = p0 + (size_t)8 * R3_;
            #pragma unroll
            for (int n = 0; n < 4; n++) {
                float v0 = d[m][l][n][0] + bv0, v1 = d[m][l][n][1] + bv0;
                float v2 = d[m][l][n][2] + bv1, v3 = d[m][l][n][3] + bv1;
                int z = n * 8 + t4 * 2;
                *(float2*)(p0 + z) = make_float2(v0, v1);
                *(float2*)(p1 + z) = make_float2(v2, v3);
                s += v0 + v1 + v2 + v3;
                s2 += v0 * v0 + v1 * v1 + v2 * v2 + v3 * v3;
            }
        }
        #pragma unroll
        for (int off = 16; off > 0; off >>= 1) {
            s += __shfl_xor_sync(0xffffffffu, s, off);
            s2 += __shfl_xor_sync(0xffffffffu, s2, off);
        }
        if (lane == 0) {
            int grp = b * NG_ + (cobase >> 4) + m;
            atomicAdd(&gs[grp], s);
            atomicAdd(&gs2[grp], s2);
        }
    }
}

// ---------------- finalize GN stats (and reset accumulators) -----------------
__global__ void gn_finalize_kernel(float* __restrict__ gs, float* __restrict__ gs2,
                                   float* __restrict__ mean, float* __restrict__ rstd) {
    int i = threadIdx.x;
    const float n = 16.0f * (float)R3_;
    float s = gs[i], s2 = gs2[i];
    float m = s / n;
    mean[i] = m;
    rstd[i] = rsqrtf(s2 / n - m * m + GN_EPS_);
    gs[i] = 0.f; gs2[i] = 0.f;
}

// ---------------- GroupNorm stats (point branch) -----------------------------
__global__ void gn_stats_kernel(const float* __restrict__ x, int S,
                                float* __restrict__ mean, float* __restrict__ rstd) {
    int bg = blockIdx.x;
    const float* p = x + (long)bg * 16 * S;
    int n = 16 * S;
    float s = 0.f, s2 = 0.f;
    for (int i = threadIdx.x; i < n; i += blockDim.x) {
        float v = p[i];
        s += v; s2 += v * v;
    }
    __shared__ float ra[512], rb[512];
    int tid = threadIdx.x;
    ra[tid] = s; rb[tid] = s2; __syncthreads();
    for (int st = 256; st > 0; st >>= 1) {
        if (tid < st) { ra[tid] += ra[tid + st]; rb[tid] += rb[tid + st]; }
        __syncthreads();
    }
    if (tid == 0) {
        float m = ra[0] / (float)n;
        float var = rb[0] / (float)n - m * m;
        mean[bg] = m;
        rstd[bg] = rsqrtf(var + GN_EPS_);
    }
}

__global__ void ptgemm_kernel(const float* __restrict__ f, const float* __restrict__ w,
                              const float* __restrict__ bias, float* __restrict__ pf) {
    int t = blockIdx.x * blockDim.x + threadIdx.x;
    int n = t & (N_ - 1);
    int r = t >> 12;
    int o = (r & 31) * 4;
    int b = r >> 5;
    float a0 = bias[o], a1 = bias[o + 1], a2 = bias[o + 2], a3 = bias[o + 3];
    const float* fb = f + (b * CIN_) * N_ + n;
    const float* w0 = w + o * CIN_;
    #pragma unroll 8
    for (int c = 0; c < CIN_; c++) {
        float fv = fb[c * N_];
        a0 += w0[c] * fv;
        a1 += w0[CIN_ + c] * fv;
        a2 += w0[2 * CIN_ + c] * fv;
        a3 += w0[3 * CIN_ + c] * fv;
    }
    float* op = &pf[(b * COUT_ + o) * N_ + n];
    op[0] = a0; op[N_] = a1; op[2 * N_] = a2; op[3 * N_] = a3;
}

// -------- devoxelize with fused GN+swish(h2) + point-branch GN/swish + add ---
__global__ void final_kernel(const float* __restrict__ nc, const float* __restrict__ h2,
                             const float* __restrict__ pf,
                             const float* __restrict__ g2g, const float* __restrict__ g2b,
                             const float* __restrict__ mean2, const float* __restrict__ rstd2,
                             const float* __restrict__ pgg, const float* __restrict__ pgb,
                             const float* __restrict__ meanp, const float* __restrict__ rstdp,
                             float* __restrict__ out) {
    int t = blockIdx.x * blockDim.x + threadIdx.x;
    int n = t & (N_ - 1);
    int r = t >> 12;
    int o = (r & 31) * 4;
    int b = r >> 5;

    float ncx = nc[(b * N_ + n) * 3 + 0];
    float ncy = nc[(b * N_ + n) * 3 + 1];
    float ncz = nc[(b * N_ + n) * 3 + 2];
    float fx = floorf(ncx), fy = floorf(ncy), fz = floorf(ncz);
    float dx = ncx - fx, dy = ncy - fy, dz = ncz - fz;
    int ix0 = (int)fx, iy0 = (int)fy, iz0 = (int)fz;
    int ix1 = min(ix0 + 1, R_ - 1), iy1 = min(iy0 + 1, R_ - 1), iz1 = min(iz0 + 1, R_ - 1);
    float wx[2] = {1.f - dx, dx}, wy[2] = {1.f - dy, dy}, wz[2] = {1.f - dz, dz};
    int xs[2] = {ix0, ix1}, ys[2] = {iy0, iy1}, zs[2] = {iz0, iz1};

    int gidx = b * NG_ + (o >> 4);
    float m2 = mean2[gidx], rs2 = rstd2[gidx];
    float ga[4], be[4];
    #pragma unroll
    for (int j = 0; j < 4; j++) { ga[j] = g2g[o + j]; be[j] = g2b[o + j]; }

    float dv[4] = {0.f, 0.f, 0.f, 0.f};
    const float* hb = &h2[(size_t)(b * COUT_ + o) * R3_];
    #pragma unroll
    for (int k = 0; k < 8; k++) {
        int kx = k >> 2, ky = (k >> 1) & 1, kz = k & 1;
        float wk = wx[kx] * wy[ky] * wz[kz];
        int id = (xs[kx] * R_ + ys[ky]) * R_ + zs[kz];
        #pragma unroll
        for (int j = 0; j < 4; j++) {
            float y = (hb[(size_t)j * R3_ + id] - m2) * rs2 * ga[j] + be[j];
            dv[j] += wk * (y / (1.0f + expf(-y)));
        }
    }

    float mp = meanp[gidx], rsp = rstdp[gidx];
    const float* pp = &pf[(b * COUT_ + o) * N_ + n];
    float* op = &out[(b * COUT_ + o) * N_ + n];
    #pragma unroll
    for (int j = 0; j < 4; j++) {
        int c = o + j;
        float y = (pp[j * N_] - mp) * rsp * pgg[c] + pgb[c];
        op[j * N_] = dv[j] + y / (1.0f + expf(-y));
    }
}

// ---------------- host launcher ----------------------------------------------
extern "C" void kernel_launch(void* const* d_in, const int* in_sizes, int n_in,
                              void* d_out, int out_size) {
    const float* features = (const float*)d_in[0];
    const float* coords   = (const float*)d_in[1];
    const float* c1w = (const float*)d_in[2];
    const float* c1b = (const float*)d_in[3];
    const float* g1g = (const float*)d_in[4];
    const float* g1b = (const float*)d_in[5];
    const float* c2w = (const float*)d_in[6];
    const float* c2b = (const float*)d_in[7];
    const float* g2g = (const float*)d_in[8];
    const float* g2b = (const float*)d_in[9];
    const float* ptw = (const float*)d_in[10];
    const float* ptb = (const float*)d_in[11];
    const float* pgg = (const float*)d_in[12];
    const float* pgb = (const float*)d_in[13];
    float* out = (float*)d_out;

    float *grid_p, *cnt_p, *h1, *h2, *pf, *nc;
    float *mean_p, *rstd_p, *mean2_p, *rstd2_p, *gs, *gs2;
    int* vox_p;
    __half *w1, *w2;
    cudaGetSymbolAddress((void**)&grid_p, g_grid);
    cudaGetSymbolAddress((void**)&cnt_p, g_cnt);
    cudaGetSymbolAddress((void**)&vox_p, g_vox);
    cudaGetSymbolAddress((void**)&nc, g_nc);
    cudaGetSymbolAddress((void**)&h1, g_h1);
    cudaGetSymbolAddress((void**)&h2, g_h2);
    cudaGetSymbolAddress((void**)&pf, g_pf);
    cudaGetSymbolAddress((void**)&mean_p, g_mean);
    cudaGetSymbolAddress((void**)&rstd_p, g_rstd);
    cudaGetSymbolAddress((void**)&mean2_p, g_mean2);
    cudaGetSymbolAddress((void**)&rstd2_p, g_rstd2);
    cudaGetSymbolAddress((void**)&gs, g_sum);
    cudaGetSymbolAddress((void**)&gs2, g_sum2);
    cudaGetSymbolAddress((void**)&w1, g_w1);
    cudaGetSymbolAddress((void**)&w2, g_w2);

    cudaFuncSetAttribute(conv3d_mma_kernel,
                         cudaFuncAttributeMaxDynamicSharedMemorySize, CONV_SMEM);

    // cnt/grid/gs start zeroed (static init on first run; cleanup at end of
    // each run restores that invariant for every graph replay).
    coords_kernel<<<B_, 256>>>(coords, nc, vox_p, cnt_p);                              // 1
    wprep2_kernel<<<(27 * 128 * (CIN_ + COUT_) + 255) / 256, 256>>>(c1w, c2w, w1, w2); // 2
    scatter_t_kernel<<<B_ * 64, 256>>>(features, vox_p, grid_p);                       // 3
    conv3d_mma_kernel<<<dim3(256, 8), 128, CONV_SMEM>>>(grid_p, w1, c1b, h1, CIN_,
        cnt_p, nullptr, nullptr, nullptr, nullptr, gs, gs2);                           // 4 <- ncu
    gn_finalize_kernel<<<1, B_ * NG_>>>(gs, gs2, mean_p, rstd_p);                      // 5
    conv3d_mma_kernel<<<dim3(256, 8), 128, CONV_SMEM>>>(h1, w2, c2b, h2, COUT_,
        nullptr, mean_p, rstd_p, g1g, g1b, gs, gs2);                                   // 6
    gn_finalize_kernel<<<1, B_ * NG_>>>(gs, gs2, mean2_p, rstd2_p);                    // 7
    ptgemm_kernel<<<4096, 256>>>(features, ptw, ptb, pf);                              // 8
    gn_stats_kernel<<<B_ * NG_, 512>>>(pf, N_, mean_p, rstd_p);                        // 9
    final_kernel<<<4096, 256>>>(nc, h2, pf, g2g, g2b, mean2_p, rstd2_p,
                                pgg, pgb, mean_p, rstd_p, out);                        // 10
    cleanup_kernel<<<B_ * N_ / 256, 256>>>(vox_p, grid_p, cnt_p);                      // 11
}

// round 12
// speedup vs baseline: 1.3333x; 1.3333x over previous
#include <cuda_runtime.h>
#include <cuda_fp16.h>
#include <math.h>
#include <stdint.h>

#define B_    8
#define N_    4096
#define CIN_  64
#define COUT_ 128
#define R_    32
#define R3_   32768
#define NG_   8
#define GN_EPS_ 1e-5f

// ---------------- scratch (static device globals; no allocation) -------------
// grid is TRANSPOSED: [b][voxel][ci]  (ci contiguous)
static __device__ float g_grid[B_ * R3_ * CIN_];
static __device__ float g_cnt [B_ * R3_];
static __device__ int   g_vox [B_ * N_];
static __device__ float g_nc  [B_ * N_ * 3];
static __device__ float g_h1  [B_ * COUT_ * R3_];
static __device__ float g_h2  [B_ * COUT_ * R3_];
static __device__ float g_pf  [B_ * COUT_ * N_];
static __device__ float g_mean [B_ * NG_];
static __device__ float g_rstd [B_ * NG_];
static __device__ float g_mean2[B_ * NG_];
static __device__ float g_rstd2[B_ * NG_];
static __device__ float g_sum [B_ * NG_];
static __device__ float g_sum2[B_ * NG_];
// W in mma A-fragment layout: [tap][chunk][cohalf][m 4][k 2][lane 32] x uint4
// conv1: 27*2*2*4*2*32 = 27648 uint4 ; conv2: 27*4*2*4*2*32 = 55296 uint4
static __device__ uint4 g_w1f[27648];
static __device__ uint4 g_w2f[55296];

// ---------------- mma.sync m16n8k16 fp16 ------------------------------------
#define MMA_F16(dd, a0, a1, a2, a3, b0, b1) \
    asm volatile("mma.sync.aligned.m16n8k16.row.col.f32.f16.f16.f32 " \
        "{%0,%1,%2,%3}, {%4,%5,%6,%7}, {%8,%9}, {%0,%1,%2,%3};" \
        : "+f"((dd)[0]), "+f"((dd)[1]), "+f"((dd)[2]), "+f"((dd)[3]) \
        : "r"(a0), "r"(a1), "r"(a2), "r"(a3), "r"(b0), "r"(b1))

__device__ __forceinline__ void ldsm4(uint32_t* r, uint32_t addr) {
    asm volatile("ldmatrix.sync.aligned.m8n8.x4.shared.b16 {%0,%1,%2,%3}, [%4];"
        : "=r"(r[0]), "=r"(r[1]), "=r"(r[2]), "=r"(r[3]) : "r"(addr));
}
__device__ __forceinline__ uint32_t smem_u32(const void* p) {
    uint32_t a;
    asm("{ .reg .u64 t; cvta.to.shared.u64 t, %1; cvt.u32.u64 %0, t; }" : "=r"(a) : "l"(p));
    return a;
}

// ============================ coords ==========================================
__global__ void coords_kernel(const float* __restrict__ coords,
                              float* __restrict__ nc, int* __restrict__ vox,
                              float* __restrict__ cnt) {
    int b = blockIdx.x, tid = threadIdx.x;
    __shared__ float red[256];
    __shared__ float smean[3];
    __shared__ float sinv;

    float s0 = 0.f, s1 = 0.f, s2 = 0.f;
    for (int n = tid; n < N_; n += 256) {
        const float* c = &coords[(b * N_ + n) * 3];
        s0 += c[0]; s1 += c[1]; s2 += c[2];
    }
    float ss[3] = {s0, s1, s2};
    for (int d = 0; d < 3; d++) {
        red[tid] = ss[d]; __syncthreads();
        for (int st = 128; st > 0; st >>= 1) {
            if (tid < st) red[tid] += red[tid + st];
            __syncthreads();
        }
        if (tid == 0) smean[d] = red[0] * (1.0f / N_);
        __syncthreads();
    }
    float m0 = smean[0], m1 = smean[1], m2 = smean[2];

    float mx = 0.f;
    for (int n = tid; n < N_; n += 256) {
        const float* c = &coords[(b * N_ + n) * 3];
        float dx = c[0] - m0, dy = c[1] - m1, dz = c[2] - m2;
        mx = fmaxf(mx, dx * dx + dy * dy + dz * dz);
    }
    red[tid] = mx; __syncthreads();
    for (int st = 128; st > 0; st >>= 1) {
        if (tid < st) red[tid] = fmaxf(red[tid], red[tid + st]);
        __syncthreads();
    }
    if (tid == 0) sinv = 1.0f / (2.0f * sqrtf(red[0]));
    __syncthreads();
    float inv = sinv;

    for (int n = tid; n < N_; n += 256) {
        const float* c = &coords[(b * N_ + n) * 3];
        float v[3]; int iv[3];
        float cc[3] = {c[0] - m0, c[1] - m1, c[2] - m2};
        #pragma unroll
        for (int d = 0; d < 3; d++) {
            float x = (cc[d] * inv + 0.5f) * (float)R_;
            x = fminf(fmaxf(x, 0.f), (float)(R_ - 1));
            v[d] = x;
            iv[d] = (int)rintf(x);
        }
        nc[(b * N_ + n) * 3 + 0] = v[0];
        nc[(b * N_ + n) * 3 + 1] = v[1];
        nc[(b * N_ + n) * 3 + 2] = v[2];
        int flat = (iv[0] * R_ + iv[1]) * R_ + iv[2];
        vox[b * N_ + n] = flat;
        atomicAdd(&cnt[b * R3_ + flat], 1.0f);
    }
}

// ---------------- weight prep: fp32 -> fp16 mma-A-fragment layout ------------
// For each (tap, ch, h, m, k, lane): uint4 of 4 regs; reg r holds half2
//   co = h*64 + m*16 + (lane>>2) + (r&1)*8
//   ci = ch*32 + k*16 + (lane&3)*2 + (r>>1)*8  (+0, +1 in the half2)
__device__ __forceinline__ void wprep_one(const float* __restrict__ w, int Cin,
                                          uint4* __restrict__ of, int idx, int nch) {
    int lane = idx & 31;
    int blk = idx >> 5;
    int k = blk & 1;
    int m = (blk >> 1) & 3;
    int h = (blk >> 3) & 1;
    int ch = (blk >> 4) % nch;
    int tap = (blk >> 4) / nch;
    int g = lane >> 2, t4 = lane & 3;
    uint32_t regs[4];
    #pragma unroll
    for (int r = 0; r < 4; r++) {
        int co = h * 64 + m * 16 + g + (r & 1) * 8;
        int ci = ch * 32 + k * 16 + t4 * 2 + (r >> 1) * 8;
        __half2 hv = __floats2half2_rn(w[(co * Cin + ci) * 27 + tap],
                                       w[(co * Cin + ci + 1) * 27 + tap]);
        regs[r] = *(uint32_t*)&hv;
    }
    of[idx] = make_uint4(regs[0], regs[1], regs[2], regs[3]);
}

__global__ void wprep2_kernel(const float* __restrict__ w1, const float* __restrict__ w2,
                              uint4* __restrict__ o1, uint4* __restrict__ o2) {
    int t = blockIdx.x * 256 + threadIdx.x;
    if (t < 27648) wprep_one(w1, CIN_, o1, t, 2);
    else if (t < 27648 + 55296) wprep_one(w2, COUT_, o2, t - 27648, 4);
}

// ---------------- scatter (smem transpose -> coalesced atomics) --------------
__global__ void scatter_t_kernel(const float* __restrict__ f,
                                 const int* __restrict__ vox,
                                 float* __restrict__ grid) {
    int b = blockIdx.x >> 6, ng = blockIdx.x & 63;
    int n0 = ng * 64;
    int tid = threadIdx.x;
    __shared__ float buf[64][65];
    #pragma unroll
    for (int k = 0; k < 16; k++) {
        int idx = k * 256 + tid;
        int c = idx >> 6, dn = idx & 63;
        buf[c][dn] = f[((size_t)b * 64 + c) * N_ + n0 + dn];
    }
    __syncthreads();
    #pragma unroll
    for (int k = 0; k < 16; k++) {
        int idx = k * 256 + tid;
        int dn = idx >> 6, c = idx & 63;
        int flat = vox[b * N_ + n0 + dn];
        atomicAdd(&grid[((size_t)b * R3_ + flat) * 64 + c], buf[c][dn]);
    }
}

// ---------------- cleanup (end of run): zero occupied grid cols + cnt --------
__global__ void cleanup_kernel(const int* __restrict__ vox,
                               float* __restrict__ grid, float* __restrict__ cnt) {
    int t = blockIdx.x * 256 + threadIdx.x;   // B*N
    int b = t >> 12;
    int flat = vox[t];
    cnt[b * R3_ + flat] = 0.f;
    float4* g4 = (float4*)&grid[((size_t)b * R3_ + flat) * 64];
    const float4 z = make_float4(0.f, 0.f, 0.f, 0.f);
    #pragma unroll
    for (int k = 0; k < 16; k++) g4[k] = z;
}

// ============================ mma.sync conv3d (fp16) =========================
// CTA: 256 thr = 8 warps. Output tile: [128 co] x [2x2 xy lines x 32 z].
// Warp w: line = w&3, cobase = (w>>2)*64. W comes via direct LDG of
// pre-arranged A-fragments: NO W smem, NO per-tap barrier.
// SMEM: X [16 line tiles][34 z][40 pad] fp16 at 0 (43,520 B)
//       flags[16] at 43,520 ; rc[512]/sscale+sshift[64] at 43,584
#define LSTRB   2720
#define FLG_OFF 43520
#define RC_OFF  43584
#define CONV_SMEM 45632

__global__ __launch_bounds__(256, 2)
void conv3d_mma_kernel(const float* __restrict__ in,
                       const uint4* __restrict__ wf,
                       const float* __restrict__ bias,
                       float* __restrict__ out, int Cin,
                       const float* __restrict__ cnt,    // conv1: transposed in + 1/cnt
                       const float* __restrict__ gnm, const float* __restrict__ gnrs,
                       const float* __restrict__ gng, const float* __restrict__ gnb,
                       float* __restrict__ gs, float* __restrict__ gs2) {
    extern __shared__ __align__(16) char smem[];
    __half* X = (__half*)smem;
    int* flags = (int*)(smem + FLG_OFF);
    float* rc = (float*)(smem + RC_OFF);
    float* sscale = (float*)(smem + RC_OFF);
    float* sshift = sscale + 32;
    uint32_t sb = smem_u32(smem);
    uint32_t x_u = sb;

    int tid = threadIdx.x, wid = tid >> 5, lane = tid & 31;
    int bx = blockIdx.x, b = blockIdx.y;
    int x0 = (bx >> 4) * 2, y0 = (bx & 15) * 2;
    int nch = Cin >> 5;
    int line = wid & 3;
    int cohalf = wid >> 2;
    int cobase = cohalf * 64;
    int g = lane >> 2, t4 = lane & 3;
    bool hc = (cnt != nullptr);

    uint32_t b_off = ((uint32_t)((lane & 7) + (lane >> 4) * 8) * 40
                      + (uint32_t)((lane >> 3) & 1) * 8) * 2;

    if (tid < 16) flags[tid] = hc ? 0 : 1;
    __syncthreads();
    if (hc) {   // per-column reciprocal counts + nonzero flags (conv1)
        for (int i = tid; i < 512; i += 256) {
            int il = i >> 5, z = i & 31;
            int gx = x0 - 1 + (il >> 2), gy = y0 - 1 + (il & 3);
            float c = 0.f;
            if ((unsigned)gx < 32u && (unsigned)gy < 32u)
                c = cnt[(size_t)b * R3_ + gx * 1024 + gy * 32 + z];
            rc[i] = __frcp_rn(fmaxf(c, 1.f));
            if (c > 0.f) flags[il] = 1;
        }
    }

    float d[4][4][4];
    #pragma unroll
    for (int m = 0; m < 4; m++)
        #pragma unroll
        for (int n = 0; n < 4; n++)
            #pragma unroll
            for (int r = 0; r < 4; r++) d[m][n][r] = 0.f;

    for (int ch = 0; ch < nch; ch++) {
        int c0 = ch * 32;
        __syncthreads();                 // prev chunk fully consumed
        if (gng) {                       // conv2: per-chunk GN scale/shift
            if (tid < 32) {
                int cc = c0 + tid;
                int gi = b * NG_ + (cc >> 4);
                float sc = gnrs[gi] * gng[cc];
                sscale[tid] = sc;
                sshift[tid] = gnb[cc] - gnm[gi] * sc;
            }
            __syncthreads();
        }
        // zero z-halo rows
        for (int i = tid; i < 1024; i += 256) {
            int ci = i & 31, r2 = (i >> 5) & 1, il = i >> 6;
            X[il * 1360 + (r2 ? 33 : 0) * 40 + ci] = __float2half_rn(0.f);
        }
        if (hc) {
            // conv1: transposed input [b][voxel][64ci]; 16 lines x 32 z x 8 ci-quads
            for (int i = tid; i < 4096; i += 256) {
                int c4 = i & 7;
                int z  = (i >> 3) & 31;
                int il = i >> 8;
                int gx = x0 - 1 + (il >> 2), gy = y0 - 1 + (il & 3);
                float4 v = make_float4(0.f, 0.f, 0.f, 0.f);
                if ((unsigned)gx < 32u && (unsigned)gy < 32u)
                    v = *(const float4*)&in[((size_t)b * R3_ + gx * 1024 + gy * 32 + z) * 64 + c0 + c4 * 4];
                float r = rc[il * 32 + z];
                int base = il * 1360 + (z + 1) * 40 + c4 * 4;
                *(__half2*)&X[base]     = __floats2half2_rn(v.x * r, v.y * r);
                *(__half2*)&X[base + 2] = __floats2half2_rn(v.z * r, v.w * r);
            }
        } else {
            // conv2: [b][c][voxel] input with fused GN+swish
            for (int i = tid; i < 4096; i += 256) {
                int zq = i & 7, ci = (i >> 3) & 31, il = i >> 8;
                int gx = x0 - 1 + (il >> 2), gy = y0 - 1 + (il & 3);
                float4 v = make_float4(0.f, 0.f, 0.f, 0.f);
                if ((unsigned)gx < 32u && (unsigned)gy < 32u)
                    v = *(const float4*)&in[(((size_t)(b * Cin + c0 + ci) * 32 + gx) * 32 + gy) * 32 + zq * 4];
                float sc = sscale[ci], sh = sshift[ci];
                int base = il * 1360 + (zq * 4 + 1) * 40 + ci;
                #pragma unroll
                for (int j = 0; j < 4; j++) {
                    float y = (&v.x)[j] * sc + sh;
                    y = y / (1.0f + expf(-y));
                    X[base + j * 40] = __float2half_rn(y);
                }
            }
        }
        __syncthreads();

        // 27 taps, NO barriers: X is read-only, W comes via LDG fragments
        const uint4* wchunk = wf + ((size_t)ch * 2 + cohalf) * 8 * 32 + lane;
        for (int tap = 0; tap < 27; tap++) {
            int dz = tap % 3, dyy = (tap / 3) % 3, dxx = tap / 9;
            int il = ((line >> 1) + dxx) * 4 + (line & 1) + dyy;
            if (flags[il]) {
                const uint4* wt = wchunk + (size_t)tap * nch * 2 * 8 * 32;
                uint32_t xb = x_u + (uint32_t)il * LSTRB + (uint32_t)dz * 80;
                uint32_t Bf[2][8];
                #pragma unroll
                for (int k = 0; k < 2; k++) {
                    ldsm4(&Bf[k][0], xb + (uint32_t)k * 32 + b_off);
                    ldsm4(&Bf[k][4], xb + 1280 + (uint32_t)k * 32 + b_off);
                }
                #pragma unroll
                for (int m = 0; m < 4; m++) {
                    #pragma unroll
                    for (int k = 0; k < 2; k++) {
                        uint4 A = wt[(m * 2 + k) * 32];
                        #pragma unroll
                        for (int n = 0; n < 4; n++)
                            MMA_F16(d[m][n], A.x, A.y, A.z, A.w,
                                    Bf[k][n * 2], Bf[k][n * 2 + 1]);
                    }
                }
            }
        }
    }

    // epilogue: write out + fused GroupNorm partial stats
    int ox = x0 + (line >> 1), oy = y0 + (line & 1);
    #pragma unroll
    for (int m = 0; m < 4; m++) {
        int co = cobase + m * 16 + g;
        float bv0 = bias[co], bv1 = bias[co + 8];
        float s = 0.f, s2 = 0.f;
        float* p0 = out + ((size_t)(b * COUT_ + co)) * R3_ + ox * 1024 + oy * 32;
        float* p1 = p0 + (size_t)8 * R3_;
        #pragma unroll
        for (int n = 0; n < 4; n++) {
            float v0 = d[m][n][0] + bv0, v1 = d[m][n][1] + bv0;
            float v2 = d[m][n][2] + bv1, v3 = d[m][n][3] + bv1;
            int z = n * 8 + t4 * 2;
            *(float2*)(p0 + z) = make_float2(v0, v1);
            *(float2*)(p1 + z) = make_float2(v2, v3);
            s += v0 + v1 + v2 + v3;
            s2 += v0 * v0 + v1 * v1 + v2 * v2 + v3 * v3;
        }
        #pragma unroll
        for (int off = 16; off > 0; off >>= 1) {
            s += __shfl_xor_sync(0xffffffffu, s, off);
            s2 += __shfl_xor_sync(0xffffffffu, s2, off);
        }
        if (lane == 0) {
            int grp = b * NG_ + (cobase >> 4) + m;
            atomicAdd(&gs[grp], s);
            atomicAdd(&gs2[grp], s2);
        }
    }
}

// ---------------- finalize GN stats (and reset accumulators) -----------------
__global__ void gn_finalize_kernel(float* __restrict__ gs, float* __restrict__ gs2,
                                   float* __restrict__ mean, float* __restrict__ rstd) {
    int i = threadIdx.x;
    const float n = 16.0f * (float)R3_;
    float s = gs[i], s2 = gs2[i];
    float m = s / n;
    mean[i] = m;
    rstd[i] = rsqrtf(s2 / n - m * m + GN_EPS_);
    gs[i] = 0.f; gs2[i] = 0.f;
}

// ---------------- GroupNorm stats (point branch) -----------------------------
__global__ void gn_stats_kernel(const float* __restrict__ x, int S,
                                float* __restrict__ mean, float* __restrict__ rstd) {
    int bg = blockIdx.x;
    const float* p = x + (long)bg * 16 * S;
    int n = 16 * S;
    float s = 0.f, s2 = 0.f;
    for (int i = threadIdx.x; i < n; i += blockDim.x) {
        float v = p[i];
        s += v; s2 += v * v;
    }
    __shared__ float ra[512], rb[512];
    int tid = threadIdx.x;
    ra[tid] = s; rb[tid] = s2; __syncthreads();
    for (int st = 256; st > 0; st >>= 1) {
        if (tid < st) { ra[tid] += ra[tid + st]; rb[tid] += rb[tid + st]; }
        __syncthreads();
    }
    if (tid == 0) {
        float m = ra[0] / (float)n;
        float var = rb[0] / (float)n - m * m;
        mean[bg] = m;
        rstd[bg] = rsqrtf(var + GN_EPS_);
    }
}

__global__ void ptgemm_kernel(const float* __restrict__ f, const float* __restrict__ w,
                              const float* __restrict__ bias, float* __restrict__ pf) {
    int t = blockIdx.x * blockDim.x + threadIdx.x;
    int n = t & (N_ - 1);
    int r = t >> 12;
    int o = (r & 31) * 4;
    int b = r >> 5;
    float a0 = bias[o], a1 = bias[o + 1], a2 = bias[o + 2], a3 = bias[o + 3];
    const float* fb = f + (b * CIN_) * N_ + n;
    const float* w0 = w + o * CIN_;
    #pragma unroll 8
    for (int c = 0; c < CIN_; c++) {
        float fv = fb[c * N_];
        a0 += w0[c] * fv;
        a1 += w0[CIN_ + c] * fv;
        a2 += w0[2 * CIN_ + c] * fv;
        a3 += w0[3 * CIN_ + c] * fv;
    }
    float* op = &pf[(b * COUT_ + o) * N_ + n];
    op[0] = a0; op[N_] = a1; op[2 * N_] = a2; op[3 * N_] = a3;
}

// -------- devoxelize with fused GN+swish(h2) + point-branch GN/swish + add ---
__global__ void final_kernel(const float* __restrict__ nc, const float* __restrict__ h2,
                             const float* __restrict__ pf,
                             const float* __restrict__ g2g, const float* __restrict__ g2b,
                             const float* __restrict__ mean2, const float* __restrict__ rstd2,
                             const float* __restrict__ pgg, const float* __restrict__ pgb,
                             const float* __restrict__ meanp, const float* __restrict__ rstdp,
                             float* __restrict__ out) {
    int t = blockIdx.x * blockDim.x + threadIdx.x;
    int n = t & (N_ - 1);
    int r = t >> 12;
    int o = (r & 31) * 4;
    int b = r >> 5;

    float ncx = nc[(b * N_ + n) * 3 + 0];
    float ncy = nc[(b * N_ + n) * 3 + 1];
    float ncz = nc[(b * N_ + n) * 3 + 2];
    float fx = floorf(ncx), fy = floorf(ncy), fz = floorf(ncz);
    float dx = ncx - fx, dy = ncy - fy, dz = ncz - fz;
    int ix0 = (int)fx, iy0 = (int)fy, iz0 = (int)fz;
    int ix1 = min(ix0 + 1, R_ - 1), iy1 = min(iy0 + 1, R_ - 1), iz1 = min(iz0 + 1, R_ - 1);
    float wx[2] = {1.f - dx, dx}, wy[2] = {1.f - dy, dy}, wz[2] = {1.f - dz, dz};
    int xs[2] = {ix0, ix1}, ys[2] = {iy0, iy1}, zs[2] = {iz0, iz1};

    int gidx = b * NG_ + (o >> 4);
    float m2 = mean2[gidx], rs2 = rstd2[gidx];
    float ga[4], be[4];
    #pragma unroll
    for (int j = 0; j < 4; j++) { ga[j] = g2g[o + j]; be[j] = g2b[o + j]; }

    float dv[4] = {0.f, 0.f, 0.f, 0.f};
    const float* hb = &h2[(size_t)(b * COUT_ + o) * R3_];
    #pragma unroll
    for (int k = 0; k < 8; k++) {
        int kx = k >> 2, ky = (k >> 1) & 1, kz = k & 1;
        float wk = wx[kx] * wy[ky] * wz[kz];
        int id = (xs[kx] * R_ + ys[ky]) * R_ + zs[kz];
        #pragma unroll
        for (int j = 0; j < 4; j++) {
            float y = (hb[(size_t)j * R3_ + id] - m2) * rs2 * ga[j] + be[j];
            dv[j] += wk * (y / (1.0f + expf(-y)));
        }
    }

    float mp = meanp[gidx], rsp = rstdp[gidx];
    const float* pp = &pf[(b * COUT_ + o) * N_ + n];
    float* op = &out[(b * COUT_ + o) * N_ + n];
    #pragma unroll
    for (int j = 0; j < 4; j++) {
        int c = o + j;
        float y = (pp[j * N_] - mp) * rsp * pgg[c] + pgb[c];
        op[j * N_] = dv[j] + y / (1.0f + expf(-y));
    }
}

// ---------------- host launcher ----------------------------------------------
extern "C" void kernel_launch(void* const* d_in, const int* in_sizes, int n_in,
                              void* d_out, int out_size) {
    const float* features = (const float*)d_in[0];
    const float* coords   = (const float*)d_in[1];
    const float* c1w = (const float*)d_in[2];
    const float* c1b = (const float*)d_in[3];
    const float* g1g = (const float*)d_in[4];
    const float* g1b = (const float*)d_in[5];
    const float* c2w = (const float*)d_in[6];
    const float* c2b = (const float*)d_in[7];
    const float* g2g = (const float*)d_in[8];
    const float* g2b = (const float*)d_in[9];
    const float* ptw = (const float*)d_in[10];
    const float* ptb = (const float*)d_in[11];
    const float* pgg = (const float*)d_in[12];
    const float* pgb = (const float*)d_in[13];
    float* out = (float*)d_out;

    float *grid_p, *cnt_p, *h1, *h2, *pf, *nc;
    float *mean_p, *rstd_p, *mean2_p, *rstd2_p, *gs, *gs2;
    int* vox_p;
    uint4 *w1f, *w2f;
    cudaGetSymbolAddress((void**)&grid_p, g_grid);
    cudaGetSymbolAddress((void**)&cnt_p, g_cnt);
    cudaGetSymbolAddress((void**)&vox_p, g_vox);
    cudaGetSymbolAddress((void**)&nc, g_nc);
    cudaGetSymbolAddress((void**)&h1, g_h1);
    cudaGetSymbolAddress((void**)&h2, g_h2);
    cudaGetSymbolAddress((void**)&pf, g_pf);
    cudaGetSymbolAddress((void**)&mean_p, g_mean);
    cudaGetSymbolAddress((void**)&rstd_p, g_rstd);
    cudaGetSymbolAddress((void**)&mean2_p, g_mean2);
    cudaGetSymbolAddress((void**)&rstd2_p, g_rstd2);
    cudaGetSymbolAddress((void**)&gs, g_sum);
    cudaGetSymbolAddress((void**)&gs2, g_sum2);
    cudaGetSymbolAddress((void**)&w1f, g_w1f);
    cudaGetSymbolAddress((void**)&w2f, g_w2f);

    cudaFuncSetAttribute(conv3d_mma_kernel,
                         cudaFuncAttributeMaxDynamicSharedMemorySize, CONV_SMEM);

    // cnt/grid/gs start zeroed (static init on first run; cleanup at end of
    // each run restores that invariant for every graph replay).
    coords_kernel<<<B_, 256>>>(coords, nc, vox_p, cnt_p);                              // 1
    wprep2_kernel<<<(27648 + 55296 + 255) / 256, 256>>>(c1w, c2w, w1f, w2f);           // 2
    scatter_t_kernel<<<B_ * 64, 256>>>(features, vox_p, grid_p);                       // 3
    conv3d_mma_kernel<<<dim3(256, 8), 256, CONV_SMEM>>>(grid_p, w1f, c1b, h1, CIN_,
        cnt_p, nullptr, nullptr, nullptr, nullptr, gs, gs2);                           // 4 <- ncu
    gn_finalize_kernel<<<1, B_ * NG_>>>(gs, gs2, mean_p, rstd_p);                      // 5
    conv3d_mma_kernel<<<dim3(256, 8), 256, CONV_SMEM>>>(h1, w2f, c2b, h2, COUT_,
        nullptr, mean_p, rstd_p, g1g, g1b, gs, gs2);                                   // 6
    gn_finalize_kernel<<<1, B_ * NG_>>>(gs, gs2, mean2_p, rstd2_p);                    // 7
    ptgemm_kernel<<<4096, 256>>>(features, ptw, ptb, pf);                              // 8
    gn_stats_kernel<<<B_ * NG_, 512>>>(pf, N_, mean_p, rstd_p);                        // 9
    final_kernel<<<4096, 256>>>(nc, h2, pf, g2g, g2b, mean2_p, rstd2_p,
                                pgg, pgb, mean_p, rstd_p, out);                        // 10
    cleanup_kernel<<<B_ * N_ / 256, 256>>>(vox_p, grid_p, cnt_p);                      // 11
}

// round 13
// speedup vs baseline: 1.3990x; 1.0493x over previous
#include <cuda_runtime.h>
#include <cuda_fp16.h>
#include <math.h>
#include <stdint.h>

#define B_    8
#define N_    4096
#define CIN_  64
#define COUT_ 128
#define R_    32
#define R3_   32768
#define NG_   8
#define GN_EPS_ 1e-5f

// ---------------- scratch (static device globals; no allocation) -------------
// grid is TRANSPOSED: [b][voxel][ci]  (ci contiguous)
static __device__ float  g_grid[B_ * R3_ * CIN_];
static __device__ float  g_cnt [B_ * R3_];
static __device__ int    g_vox [B_ * N_];
static __device__ float  g_nc  [B_ * N_ * 3];
static __device__ __half g_h1  [B_ * COUT_ * R3_];   // fp16, channel-major
static __device__ __half g_h2  [B_ * R3_ * COUT_];   // fp16, channel-LAST
static __device__ float  g_pf  [B_ * COUT_ * N_];
static __device__ float  g_mean [B_ * NG_];
static __device__ float  g_rstd [B_ * NG_];
static __device__ float  g_mean2[B_ * NG_];
static __device__ float  g_rstd2[B_ * NG_];
static __device__ float  g_sum [B_ * NG_];
static __device__ float  g_sum2[B_ * NG_];
// W in mma A-fragment layout: [tap][chunk][cohalf][m 4][k 2][lane 32] x uint4
static __device__ uint4 g_w1f[27648];
static __device__ uint4 g_w2f[55296];

// ---------------- mma.sync m16n8k16 fp16 ------------------------------------
#define MMA_F16(dd, a0, a1, a2, a3, b0, b1) \
    asm volatile("mma.sync.aligned.m16n8k16.row.col.f32.f16.f16.f32 " \
        "{%0,%1,%2,%3}, {%4,%5,%6,%7}, {%8,%9}, {%0,%1,%2,%3};" \
        : "+f"((dd)[0]), "+f"((dd)[1]), "+f"((dd)[2]), "+f"((dd)[3]) \
        : "r"(a0), "r"(a1), "r"(a2), "r"(a3), "r"(b0), "r"(b1))

__device__ __forceinline__ void ldsm4(uint32_t* r, uint32_t addr) {
    asm volatile("ldmatrix.sync.aligned.m8n8.x4.shared.b16 {%0,%1,%2,%3}, [%4];"
        : "=r"(r[0]), "=r"(r[1]), "=r"(r[2]), "=r"(r[3]) : "r"(addr));
}
__device__ __forceinline__ uint32_t smem_u32(const void* p) {
    uint32_t a;
    asm("{ .reg .u64 t; cvta.to.shared.u64 t, %1; cvt.u32.u64 %0, t; }" : "=r"(a) : "l"(p));
    return a;
}

// ============================ coords ==========================================
__global__ void coords_kernel(const float* __restrict__ coords,
                              float* __restrict__ nc, int* __restrict__ vox,
                              float* __restrict__ cnt) {
    int b = blockIdx.x, tid = threadIdx.x;
    __shared__ float red[256];
    __shared__ float smean[3];
    __shared__ float sinv;

    float s0 = 0.f, s1 = 0.f, s2 = 0.f;
    for (int n = tid; n < N_; n += 256) {
        const float* c = &coords[(b * N_ + n) * 3];
        s0 += c[0]; s1 += c[1]; s2 += c[2];
    }
    float ss[3] = {s0, s1, s2};
    for (int d = 0; d < 3; d++) {
        red[tid] = ss[d]; __syncthreads();
        for (int st = 128; st > 0; st >>= 1) {
            if (tid < st) red[tid] += red[tid + st];
            __syncthreads();
        }
        if (tid == 0) smean[d] = red[0] * (1.0f / N_);
        __syncthreads();
    }
    float m0 = smean[0], m1 = smean[1], m2 = smean[2];

    float mx = 0.f;
    for (int n = tid; n < N_; n += 256) {
        const float* c = &coords[(b * N_ + n) * 3];
        float dx = c[0] - m0, dy = c[1] - m1, dz = c[2] - m2;
        mx = fmaxf(mx, dx * dx + dy * dy + dz * dz);
    }
    red[tid] = mx; __syncthreads();
    for (int st = 128; st > 0; st >>= 1) {
        if (tid < st) red[tid] = fmaxf(red[tid], red[tid + st]);
        __syncthreads();
    }
    if (tid == 0) sinv = 1.0f / (2.0f * sqrtf(red[0]));
    __syncthreads();
    float inv = sinv;

    for (int n = tid; n < N_; n += 256) {
        const float* c = &coords[(b * N_ + n) * 3];
        float v[3]; int iv[3];
        float cc[3] = {c[0] - m0, c[1] - m1, c[2] - m2};
        #pragma unroll
        for (int d = 0; d < 3; d++) {
            float x = (cc[d] * inv + 0.5f) * (float)R_;
            x = fminf(fmaxf(x, 0.f), (float)(R_ - 1));
            v[d] = x;
            iv[d] = (int)rintf(x);
        }
        nc[(b * N_ + n) * 3 + 0] = v[0];
        nc[(b * N_ + n) * 3 + 1] = v[1];
        nc[(b * N_ + n) * 3 + 2] = v[2];
        int flat = (iv[0] * R_ + iv[1]) * R_ + iv[2];
        vox[b * N_ + n] = flat;
        atomicAdd(&cnt[b * R3_ + flat], 1.0f);
    }
}

// ---------------- weight prep: fp32 -> fp16 mma-A-fragment layout ------------
__device__ __forceinline__ void wprep_one(const float* __restrict__ w, int Cin,
                                          uint4* __restrict__ of, int idx, int nch) {
    int lane = idx & 31;
    int blk = idx >> 5;
    int k = blk & 1;
    int m = (blk >> 1) & 3;
    int h = (blk >> 3) & 1;
    int ch = (blk >> 4) % nch;
    int tap = (blk >> 4) / nch;
    int g = lane >> 2, t4 = lane & 3;
    uint32_t regs[4];
    #pragma unroll
    for (int r = 0; r < 4; r++) {
        int co = h * 64 + m * 16 + g + (r & 1) * 8;
        int ci = ch * 32 + k * 16 + t4 * 2 + (r >> 1) * 8;
        __half2 hv = __floats2half2_rn(w[(co * Cin + ci) * 27 + tap],
                                       w[(co * Cin + ci + 1) * 27 + tap]);
        regs[r] = *(uint32_t*)&hv;
    }
    of[idx] = make_uint4(regs[0], regs[1], regs[2], regs[3]);
}

__global__ void wprep2_kernel(const float* __restrict__ w1, const float* __restrict__ w2,
                              uint4* __restrict__ o1, uint4* __restrict__ o2) {
    int t = blockIdx.x * 256 + threadIdx.x;
    if (t < 27648) wprep_one(w1, CIN_, o1, t, 2);
    else if (t < 27648 + 55296) wprep_one(w2, COUT_, o2, t - 27648, 4);
}

// ---------------- scatter (smem transpose -> coalesced atomics) --------------
__global__ void scatter_t_kernel(const float* __restrict__ f,
                                 const int* __restrict__ vox,
                                 float* __restrict__ grid) {
    int b = blockIdx.x >> 6, ng = blockIdx.x & 63;
    int n0 = ng * 64;
    int tid = threadIdx.x;
    __shared__ float buf[64][65];
    #pragma unroll
    for (int k = 0; k < 16; k++) {
        int idx = k * 256 + tid;
        int c = idx >> 6, dn = idx & 63;
        buf[c][dn] = f[((size_t)b * 64 + c) * N_ + n0 + dn];
    }
    __syncthreads();
    #pragma unroll
    for (int k = 0; k < 16; k++) {
        int idx = k * 256 + tid;
        int dn = idx >> 6, c = idx & 63;
        int flat = vox[b * N_ + n0 + dn];
        atomicAdd(&grid[((size_t)b * R3_ + flat) * 64 + c], buf[c][dn]);
    }
}

// ---------------- cleanup (end of run): zero occupied grid cols + cnt --------
__global__ void cleanup_kernel(const int* __restrict__ vox,
                               float* __restrict__ grid, float* __restrict__ cnt) {
    int t = blockIdx.x * 256 + threadIdx.x;   // B*N
    int b = t >> 12;
    int flat = vox[t];
    cnt[b * R3_ + flat] = 0.f;
    float4* g4 = (float4*)&grid[((size_t)b * R3_ + flat) * 64];
    const float4 z = make_float4(0.f, 0.f, 0.f, 0.f);
    #pragma unroll
    for (int k = 0; k < 16; k++) g4[k] = z;
}

// ============================ mma.sync conv3d (fp16) =========================
// CTA: 256 thr = 8 warps. Output tile: [128 co] x [2x2 xy lines x 32 z].
// Direct-LDG W fragments (no W smem, no per-tap barrier).
// conv1 (hc): in = float grid [b][voxel][64ci], out = h1 fp16 channel-major.
// conv2:      in = h1 fp16 [b][c][voxel] (GN+swish fused in staging),
//             out = h2 fp16 channel-LAST via smem-transposed epilogue.
#define LSTRB   2720
#define FLG_OFF 43520
#define RC_OFF  43584
#define CONV_SMEM 45632

__global__ __launch_bounds__(256, 2)
void conv3d_mma_kernel(const void* __restrict__ in,
                       const uint4* __restrict__ wf,
                       const float* __restrict__ bias,
                       __half* __restrict__ out, int Cin,
                       const float* __restrict__ cnt,
                       const float* __restrict__ gnm, const float* __restrict__ gnrs,
                       const float* __restrict__ gng, const float* __restrict__ gnb,
                       float* __restrict__ gs, float* __restrict__ gs2) {
    extern __shared__ __align__(16) char smem[];
    __half* X = (__half*)smem;
    int* flags = (int*)(smem + FLG_OFF);
    float* rc = (float*)(smem + RC_OFF);
    float* sscale = (float*)(smem + RC_OFF);
    float* sshift = sscale + 32;
    uint32_t sb = smem_u32(smem);
    uint32_t x_u = sb;

    int tid = threadIdx.x, wid = tid >> 5, lane = tid & 31;
    int bx = blockIdx.x, b = blockIdx.y;
    int x0 = (bx >> 4) * 2, y0 = (bx & 15) * 2;
    int nch = Cin >> 5;
    int line = wid & 3;
    int cohalf = wid >> 2;
    int cobase = cohalf * 64;
    int g = lane >> 2, t4 = lane & 3;
    bool hc = (cnt != nullptr);

    uint32_t b_off = ((uint32_t)((lane & 7) + (lane >> 4) * 8) * 40
                      + (uint32_t)((lane >> 3) & 1) * 8) * 2;

    if (tid < 16) flags[tid] = hc ? 0 : 1;
    __syncthreads();
    if (hc) {   // per-column reciprocal counts + nonzero flags (conv1)
        for (int i = tid; i < 512; i += 256) {
            int il = i >> 5, z = i & 31;
            int gx = x0 - 1 + (il >> 2), gy = y0 - 1 + (il & 3);
            float c = 0.f;
            if ((unsigned)gx < 32u && (unsigned)gy < 32u)
                c = cnt[(size_t)b * R3_ + gx * 1024 + gy * 32 + z];
            rc[i] = __frcp_rn(fmaxf(c, 1.f));
            if (c > 0.f) flags[il] = 1;
        }
    }

    float d[4][4][4];
    #pragma unroll
    for (int m = 0; m < 4; m++)
        #pragma unroll
        for (int n = 0; n < 4; n++)
            #pragma unroll
            for (int r = 0; r < 4; r++) d[m][n][r] = 0.f;

    for (int ch = 0; ch < nch; ch++) {
        int c0 = ch * 32;
        __syncthreads();                 // prev chunk fully consumed
        if (!hc) {                       // conv2: per-chunk GN scale/shift
            if (tid < 32) {
                int cc = c0 + tid;
                int gi = b * NG_ + (cc >> 4);
                float sc = gnrs[gi] * gng[cc];
                sscale[tid] = sc;
                sshift[tid] = gnb[cc] - gnm[gi] * sc;
            }
            __syncthreads();
        }
        // zero z-halo rows
        for (int i = tid; i < 1024; i += 256) {
            int ci = i & 31, r2 = (i >> 5) & 1, il = i >> 6;
            X[il * 1360 + (r2 ? 33 : 0) * 40 + ci] = __float2half_rn(0.f);
        }
        if (hc) {
            // conv1: transposed float input [b][voxel][64ci]
            const float* inf = (const float*)in;
            for (int i = tid; i < 4096; i += 256) {
                int c4 = i & 7;
                int z  = (i >> 3) & 31;
                int il = i >> 8;
                int gx = x0 - 1 + (il >> 2), gy = y0 - 1 + (il & 3);
                float4 v = make_float4(0.f, 0.f, 0.f, 0.f);
                if ((unsigned)gx < 32u && (unsigned)gy < 32u)
                    v = *(const float4*)&inf[((size_t)b * R3_ + gx * 1024 + gy * 32 + z) * 64 + c0 + c4 * 4];
                float r = rc[il * 32 + z];
                int base = il * 1360 + (z + 1) * 40 + c4 * 4;
                *(__half2*)&X[base]     = __floats2half2_rn(v.x * r, v.y * r);
                *(__half2*)&X[base + 2] = __floats2half2_rn(v.z * r, v.w * r);
            }
        } else {
            // conv2: fp16 [b][c][voxel] input with fused GN+swish
            const __half* inh = (const __half*)in;
            for (int i = tid; i < 4096; i += 256) {
                int zq = i & 7, ci = (i >> 3) & 31, il = i >> 8;
                int gx = x0 - 1 + (il >> 2), gy = y0 - 1 + (il & 3);
                float f[4] = {0.f, 0.f, 0.f, 0.f};
                if ((unsigned)gx < 32u && (unsigned)gy < 32u) {
                    uint2 raw = *(const uint2*)&inh[((size_t)(b * Cin + c0 + ci)) * R3_
                                                    + gx * 1024 + gy * 32 + zq * 4];
                    __half2 a01 = *(__half2*)&raw.x, a23 = *(__half2*)&raw.y;
                    f[0] = __low2float(a01); f[1] = __high2float(a01);
                    f[2] = __low2float(a23); f[3] = __high2float(a23);
                }
                float sc = sscale[ci], sh = sshift[ci];
                int base = il * 1360 + (zq * 4 + 1) * 40 + ci;
                #pragma unroll
                for (int j = 0; j < 4; j++) {
                    float y = f[j] * sc + sh;
                    y = y / (1.0f + expf(-y));
                    X[base + j * 40] = __float2half_rn(y);
                }
            }
        }
        __syncthreads();

        // 27 taps, NO barriers: X read-only, W via LDG fragments
        const uint4* wchunk = wf + ((size_t)ch * 2 + cohalf) * 8 * 32 + lane;
        for (int tap = 0; tap < 27; tap++) {
            int dz = tap % 3, dyy = (tap / 3) % 3, dxx = tap / 9;
            int il = ((line >> 1) + dxx) * 4 + (line & 1) + dyy;
            if (flags[il]) {
                const uint4* wt = wchunk + (size_t)tap * nch * 2 * 8 * 32;
                uint32_t xb = x_u + (uint32_t)il * LSTRB + (uint32_t)dz * 80;
                uint32_t Bf[2][8];
                #pragma unroll
                for (int k = 0; k < 2; k++) {
                    ldsm4(&Bf[k][0], xb + (uint32_t)k * 32 + b_off);
                    ldsm4(&Bf[k][4], xb + 1280 + (uint32_t)k * 32 + b_off);
                }
                #pragma unroll
                for (int m = 0; m < 4; m++) {
                    #pragma unroll
                    for (int k = 0; k < 2; k++) {
                        uint4 A = wt[(m * 2 + k) * 32];
                        #pragma unroll
                        for (int n = 0; n < 4; n++)
                            MMA_F16(d[m][n], A.x, A.y, A.z, A.w,
                                    Bf[k][n * 2], Bf[k][n * 2 + 1]);
                    }
                }
            }
        }
    }

    // ---------------- epilogue -------------------------------------------------
    if (hc) {
        // conv1: fp16 channel-major out + fused GN partial stats
        int ox = x0 + (line >> 1), oy = y0 + (line & 1);
        #pragma unroll
        for (int m = 0; m < 4; m++) {
            int co = cobase + m * 16 + g;
            float bv0 = bias[co], bv1 = bias[co + 8];
            float s = 0.f, s2 = 0.f;
            __half* p0 = out + ((size_t)(b * COUT_ + co)) * R3_ + ox * 1024 + oy * 32;
            __half* p1 = p0 + (size_t)8 * R3_;
            #pragma unroll
            for (int n = 0; n < 4; n++) {
                float v0 = d[m][n][0] + bv0, v1 = d[m][n][1] + bv0;
                float v2 = d[m][n][2] + bv1, v3 = d[m][n][3] + bv1;
                int z = n * 8 + t4 * 2;
                *(__half2*)(p0 + z) = __floats2half2_rn(v0, v1);
                *(__half2*)(p1 + z) = __floats2half2_rn(v2, v3);
                s += v0 + v1 + v2 + v3;
                s2 += v0 * v0 + v1 * v1 + v2 * v2 + v3 * v3;
            }
            #pragma unroll
            for (int off = 16; off > 0; off >>= 1) {
                s += __shfl_xor_sync(0xffffffffu, s, off);
                s2 += __shfl_xor_sync(0xffffffffu, s2, off);
            }
            if (lane == 0) {
                int grp = b * NG_ + (cobase >> 4) + m;
                atomicAdd(&gs[grp], s);
                atomicAdd(&gs2[grp], s2);
            }
        }
    } else {
        // conv2: smem-transpose to channel-last fp16 + fused GN partial stats
        __syncthreads();                 // X no longer needed; reuse as T
        __half* T = (__half*)smem;       // [4 lines][32 z][128 co]
        #pragma unroll
        for (int m = 0; m < 4; m++) {
            int co = cobase + m * 16 + g;
            float bv0 = bias[co], bv1 = bias[co + 8];
            float s = 0.f, s2 = 0.f;
            #pragma unroll
            for (int n = 0; n < 4; n++) {
                float v0 = d[m][n][0] + bv0, v1 = d[m][n][1] + bv0;
                float v2 = d[m][n][2] + bv1, v3 = d[m][n][3] + bv1;
                int z = n * 8 + t4 * 2;
                __half* tb = T + (size_t)line * 4096;
                tb[(z) * 128 + co]     = __float2half_rn(v0);
                tb[(z + 1) * 128 + co] = __float2half_rn(v1);
                tb[(z) * 128 + co + 8]     = __float2half_rn(v2);
                tb[(z + 1) * 128 + co + 8] = __float2half_rn(v3);
                s += v0 + v1 + v2 + v3;
                s2 += v0 * v0 + v1 * v1 + v2 * v2 + v3 * v3;
            }
            #pragma unroll
            for (int off = 16; off > 0; off >>= 1) {
                s += __shfl_xor_sync(0xffffffffu, s, off);
                s2 += __shfl_xor_sync(0xffffffffu, s2, off);
            }
            if (lane == 0) {
                int grp = b * NG_ + (cobase >> 4) + m;
                atomicAdd(&gs[grp], s);
                atomicAdd(&gs2[grp], s2);
            }
        }
        __syncthreads();
        // coalesced copy-out: 4 line blocks x 512 uint4 (8KB each, contiguous)
        const uint4* Tv = (const uint4*)T;
        for (int i = tid; i < 2048; i += 256) {
            int l = i >> 9, j = i & 511;
            int ox = x0 + (l >> 1), oy = y0 + (l & 1);
            uint4* dst = (uint4*)(out + ((size_t)b * R3_ + ox * 1024 + oy * 32) * 128);
            dst[j] = Tv[i];
        }
    }
}

// ---------------- finalize GN stats (and reset accumulators) -----------------
__global__ void gn_finalize_kernel(float* __restrict__ gs, float* __restrict__ gs2,
                                   float* __restrict__ mean, float* __restrict__ rstd) {
    int i = threadIdx.x;
    const float n = 16.0f * (float)R3_;
    float s = gs[i], s2 = gs2[i];
    float m = s / n;
    mean[i] = m;
    rstd[i] = rsqrtf(s2 / n - m * m + GN_EPS_);
    gs[i] = 0.f; gs2[i] = 0.f;
}

// ---------------- GroupNorm stats (point branch) -----------------------------
__global__ void gn_stats_kernel(const float* __restrict__ x, int S,
                                float* __restrict__ mean, float* __restrict__ rstd) {
    int bg = blockIdx.x;
    const float* p = x + (long)bg * 16 * S;
    int n = 16 * S;
    float s = 0.f, s2 = 0.f;
    for (int i = threadIdx.x; i < n; i += blockDim.x) {
        float v = p[i];
        s += v; s2 += v * v;
    }
    __shared__ float ra[512], rb[512];
    int tid = threadIdx.x;
    ra[tid] = s; rb[tid] = s2; __syncthreads();
    for (int st = 256; st > 0; st >>= 1) {
        if (tid < st) { ra[tid] += ra[tid + st]; rb[tid] += rb[tid + st]; }
        __syncthreads();
    }
    if (tid == 0) {
        float m = ra[0] / (float)n;
        float var = rb[0] / (float)n - m * m;
        mean[bg] = m;
        rstd[bg] = rsqrtf(var + GN_EPS_);
    }
}

__global__ void ptgemm_kernel(const float* __restrict__ f, const float* __restrict__ w,
                              const float* __restrict__ bias, float* __restrict__ pf) {
    int t = blockIdx.x * blockDim.x + threadIdx.x;
    int n = t & (N_ - 1);
    int r = t >> 12;
    int o = (r & 31) * 4;
    int b = r >> 5;
    float a0 = bias[o], a1 = bias[o + 1], a2 = bias[o + 2], a3 = bias[o + 3];
    const float* fb = f + (b * CIN_) * N_ + n;
    const float* w0 = w + o * CIN_;
    #pragma unroll 8
    for (int c = 0; c < CIN_; c++) {
        float fv = fb[c * N_];
        a0 += w0[c] * fv;
        a1 += w0[CIN_ + c] * fv;
        a2 += w0[2 * CIN_ + c] * fv;
        a3 += w0[3 * CIN_ + c] * fv;
    }
    float* op = &pf[(b * COUT_ + o) * N_ + n];
    op[0] = a0; op[N_] = a1; op[2 * N_] = a2; op[3 * N_] = a3;
}

// -------- devoxelize (fp16 channel-last h2, fused GN+swish) + point branch ---
__global__ void final_kernel(const float* __restrict__ nc, const __half* __restrict__ h2,
                             const float* __restrict__ pf,
                             const float* __restrict__ g2g, const float* __restrict__ g2b,
                             const float* __restrict__ mean2, const float* __restrict__ rstd2,
                             const float* __restrict__ pgg, const float* __restrict__ pgb,
                             const float* __restrict__ meanp, const float* __restrict__ rstdp,
                             float* __restrict__ out) {
    int t = blockIdx.x * blockDim.x + threadIdx.x;
    int n = t & (N_ - 1);
    int r = t >> 12;
    int o = (r & 31) * 4;
    int b = r >> 5;

    float ncx = nc[(b * N_ + n) * 3 + 0];
    float ncy = nc[(b * N_ + n) * 3 + 1];
    float ncz = nc[(b * N_ + n) * 3 + 2];
    float fx = floorf(ncx), fy = floorf(ncy), fz = floorf(ncz);
    float dx = ncx - fx, dy = ncy - fy, dz = ncz - fz;
    int ix0 = (int)fx, iy0 = (int)fy, iz0 = (int)fz;
    int ix1 = min(ix0 + 1, R_ - 1), iy1 = min(iy0 + 1, R_ - 1), iz1 = min(iz0 + 1, R_ - 1);
    float wx[2] = {1.f - dx, dx}, wy[2] = {1.f - dy, dy}, wz[2] = {1.f - dz, dz};
    int xs[2] = {ix0, ix1}, ys[2] = {iy0, iy1}, zs[2] = {iz0, iz1};

    int gidx = b * NG_ + (o >> 4);
    float m2 = mean2[gidx], rs2 = rstd2[gidx];
    float ga[4], be[4];
    #pragma unroll
    for (int j = 0; j < 4; j++) { ga[j] = g2g[o + j]; be[j] = g2b[o + j]; }

    float dv[4] = {0.f, 0.f, 0.f, 0.f};
    const __half* hb = h2 + ((size_t)b * R3_) * 128;
    #pragma unroll
    for (int k = 0; k < 8; k++) {
        int kx = k >> 2, ky = (k >> 1) & 1, kz = k & 1;
        float wk = wx[kx] * wy[ky] * wz[kz];
        int id = (xs[kx] * R_ + ys[ky]) * R_ + zs[kz];
        uint2 raw = *(const uint2*)&hb[(size_t)id * 128 + o];
        __half2 a01 = *(__half2*)&raw.x, a23 = *(__half2*)&raw.y;
        float hv[4] = {__low2float(a01), __high2float(a01),
                       __low2float(a23), __high2float(a23)};
        #pragma unroll
        for (int j = 0; j < 4; j++) {
            float y = (hv[j] - m2) * rs2 * ga[j] + be[j];
            dv[j] += wk * (y / (1.0f + expf(-y)));
        }
    }

    float mp = meanp[gidx], rsp = rstdp[gidx];
    const float* pp = &pf[(b * COUT_ + o) * N_ + n];
    float* op = &out[(b * COUT_ + o) * N_ + n];
    #pragma unroll
    for (int j = 0; j < 4; j++) {
        int c = o + j;
        float y = (pp[j * N_] - mp) * rsp * pgg[c] + pgb[c];
        op[j * N_] = dv[j] + y / (1.0f + expf(-y));
    }
}

// ---------------- host launcher ----------------------------------------------
extern "C" void kernel_launch(void* const* d_in, const int* in_sizes, int n_in,
                              void* d_out, int out_size) {
    const float* features = (const float*)d_in[0];
    const float* coords   = (const float*)d_in[1];
    const float* c1w = (const float*)d_in[2];
    const float* c1b = (const float*)d_in[3];
    const float* g1g = (const float*)d_in[4];
    const float* g1b = (const float*)d_in[5];
    const float* c2w = (const float*)d_in[6];
    const float* c2b = (const float*)d_in[7];
    const float* g2g = (const float*)d_in[8];
    const float* g2b = (const float*)d_in[9];
    const float* ptw = (const float*)d_in[10];
    const float* ptb = (const float*)d_in[11];
    const float* pgg = (const float*)d_in[12];
    const float* pgb = (const float*)d_in[13];
    float* out = (float*)d_out;

    float *grid_p, *cnt_p, *pf, *nc;
    float *mean_p, *rstd_p, *mean2_p, *rstd2_p, *gs, *gs2;
    __half *h1, *h2;
    int* vox_p;
    uint4 *w1f, *w2f;
    cudaGetSymbolAddress((void**)&grid_p, g_grid);
    cudaGetSymbolAddress((void**)&cnt_p, g_cnt);
    cudaGetSymbolAddress((void**)&vox_p, g_vox);
    cudaGetSymbolAddress((void**)&nc, g_nc);
    cudaGetSymbolAddress((void**)&h1, g_h1);
    cudaGetSymbolAddress((void**)&h2, g_h2);
    cudaGetSymbolAddress((void**)&pf, g_pf);
    cudaGetSymbolAddress((void**)&mean_p, g_mean);
    cudaGetSymbolAddress((void**)&rstd_p, g_rstd);
    cudaGetSymbolAddress((void**)&mean2_p, g_mean2);
    cudaGetSymbolAddress((void**)&rstd2_p, g_rstd2);
    cudaGetSymbolAddress((void**)&gs, g_sum);
    cudaGetSymbolAddress((void**)&gs2, g_sum2);
    cudaGetSymbolAddress((void**)&w1f, g_w1f);
    cudaGetSymbolAddress((void**)&w2f, g_w2f);

    cudaFuncSetAttribute(conv3d_mma_kernel,
                         cudaFuncAttributeMaxDynamicSharedMemorySize, CONV_SMEM);

    // cnt/grid/gs start zeroed (static init on first run; cleanup at end of
    // each run restores that invariant for every graph replay).
    coords_kernel<<<B_, 256>>>(coords, nc, vox_p, cnt_p);                              // 1
    wprep2_kernel<<<(27648 + 55296 + 255) / 256, 256>>>(c1w, c2w, w1f, w2f);           // 2
    scatter_t_kernel<<<B_ * 64, 256>>>(features, vox_p, grid_p);                       // 3
    conv3d_mma_kernel<<<dim3(256, 8), 256, CONV_SMEM>>>(grid_p, w1f, c1b, h1, CIN_,
        cnt_p, nullptr, nullptr, nullptr, nullptr, gs, gs2);                           // 4 <- ncu
    gn_finalize_kernel<<<1, B_ * NG_>>>(gs, gs2, mean_p, rstd_p);                      // 5
    conv3d_mma_kernel<<<dim3(256, 8), 256, CONV_SMEM>>>(h1, w2f, c2b, h2, COUT_,
        nullptr, mean_p, rstd_p, g1g, g1b, gs, gs2);                                   // 6
    gn_finalize_kernel<<<1, B_ * NG_>>>(gs, gs2, mean2_p, rstd2_p);                    // 7
    ptgemm_kernel<<<4096, 256>>>(features, ptw, ptb, pf);                              // 8
    gn_stats_kernel<<<B_ * NG_, 512>>>(pf, N_, mean_p, rstd_p);                        // 9
    final_kernel<<<4096, 256>>>(nc, h2, pf, g2g, g2b, mean2_p, rstd2_p,
                                pgg, pgb, mean_p, rstd_p, out);                        // 10
    cleanup_kernel<<<B_ * N_ / 256, 256>>>(vox_p, grid_p, cnt_p);                      // 11
}

// round 14
// speedup vs baseline: 1.7156x; 1.2263x over previous
#include <cuda_runtime.h>
#include <cuda_fp16.h>
#include <math.h>
#include <stdint.h>

#define B_    8
#define N_    4096
#define CIN_  64
#define COUT_ 128
#define R_    32
#define R3_   32768
#define NG_   8
#define GN_EPS_ 1e-5f

// ---------------- scratch (static device globals; no allocation) -------------
static __device__ float  g_grid[B_ * R3_ * CIN_];    // [b][voxel][ci]
static __device__ float  g_cnt [B_ * R3_];
static __device__ int    g_vox [B_ * N_];
static __device__ float  g_nc  [B_ * N_ * 3];
static __device__ __half g_h1  [B_ * COUT_ * R3_];   // fp16, channel-major
static __device__ __half g_h2  [B_ * R3_ * COUT_];   // fp16, channel-LAST
static __device__ float  g_pf  [B_ * COUT_ * N_];
static __device__ float  g_mean [B_ * NG_];
static __device__ float  g_rstd [B_ * NG_];
static __device__ float  g_mean2[B_ * NG_];
static __device__ float  g_rstd2[B_ * NG_];
static __device__ float  g_sum [B_ * NG_];
static __device__ float  g_sum2[B_ * NG_];
// W in mma A-fragment layout: [tap][chunk][cohalf][m 4][k 2][lane 32] x uint4
static __device__ uint4 g_w1f[27648];
static __device__ uint4 g_w2f[55296];

// ---------------- mma.sync m16n8k16 fp16 ------------------------------------
#define MMA_F16(dd, a0, a1, a2, a3, b0, b1) \
    asm volatile("mma.sync.aligned.m16n8k16.row.col.f32.f16.f16.f32 " \
        "{%0,%1,%2,%3}, {%4,%5,%6,%7}, {%8,%9}, {%0,%1,%2,%3};" \
        : "+f"((dd)[0]), "+f"((dd)[1]), "+f"((dd)[2]), "+f"((dd)[3]) \
        : "r"(a0), "r"(a1), "r"(a2), "r"(a3), "r"(b0), "r"(b1))

__device__ __forceinline__ void ldsm4(uint32_t* r, uint32_t addr) {
    asm volatile("ldmatrix.sync.aligned.m8n8.x4.shared.b16 {%0,%1,%2,%3}, [%4];"
        : "=r"(r[0]), "=r"(r[1]), "=r"(r[2]), "=r"(r[3]) : "r"(addr));
}
__device__ __forceinline__ uint32_t smem_u32(const void* p) {
    uint32_t a;
    asm("{ .reg .u64 t; cvta.to.shared.u64 t, %1; cvt.u32.u64 %0, t; }" : "=r"(a) : "l"(p));
    return a;
}
__device__ __forceinline__ float fast_swish(float y) {
    return y / (1.0f + __expf(-y));
}

// ============================ coords ==========================================
__global__ void coords_kernel(const float* __restrict__ coords,
                              float* __restrict__ nc, int* __restrict__ vox,
                              float* __restrict__ cnt) {
    int b = blockIdx.x, tid = threadIdx.x;
    __shared__ float red[256];
    __shared__ float smean[3];
    __shared__ float sinv;

    float s0 = 0.f, s1 = 0.f, s2 = 0.f;
    for (int n = tid; n < N_; n += 256) {
        const float* c = &coords[(b * N_ + n) * 3];
        s0 += c[0]; s1 += c[1]; s2 += c[2];
    }
    float ss[3] = {s0, s1, s2};
    for (int d = 0; d < 3; d++) {
        red[tid] = ss[d]; __syncthreads();
        for (int st = 128; st > 0; st >>= 1) {
            if (tid < st) red[tid] += red[tid + st];
            __syncthreads();
        }
        if (tid == 0) smean[d] = red[0] * (1.0f / N_);
        __syncthreads();
    }
    float m0 = smean[0], m1 = smean[1], m2 = smean[2];

    float mx = 0.f;
    for (int n = tid; n < N_; n += 256) {
        const float* c = &coords[(b * N_ + n) * 3];
        float dx = c[0] - m0, dy = c[1] - m1, dz = c[2] - m2;
        mx = fmaxf(mx, dx * dx + dy * dy + dz * dz);
    }
    red[tid] = mx; __syncthreads();
    for (int st = 128; st > 0; st >>= 1) {
        if (tid < st) red[tid] = fmaxf(red[tid], red[tid + st]);
        __syncthreads();
    }
    if (tid == 0) sinv = 1.0f / (2.0f * sqrtf(red[0]));
    __syncthreads();
    float inv = sinv;

    for (int n = tid; n < N_; n += 256) {
        const float* c = &coords[(b * N_ + n) * 3];
        float v[3]; int iv[3];
        float cc[3] = {c[0] - m0, c[1] - m1, c[2] - m2};
        #pragma unroll
        for (int d = 0; d < 3; d++) {
            float x = (cc[d] * inv + 0.5f) * (float)R_;
            x = fminf(fmaxf(x, 0.f), (float)(R_ - 1));
            v[d] = x;
            iv[d] = (int)rintf(x);
        }
        nc[(b * N_ + n) * 3 + 0] = v[0];
        nc[(b * N_ + n) * 3 + 1] = v[1];
        nc[(b * N_ + n) * 3 + 2] = v[2];
        int flat = (iv[0] * R_ + iv[1]) * R_ + iv[2];
        vox[b * N_ + n] = flat;
        atomicAdd(&cnt[b * R3_ + flat], 1.0f);
    }
}

// ---------------- weight prep: fp32 -> fp16 mma-A-fragment layout ------------
__device__ __forceinline__ void wprep_one(const float* __restrict__ w, int Cin,
                                          uint4* __restrict__ of, int idx, int nch) {
    int lane = idx & 31;
    int blk = idx >> 5;
    int k = blk & 1;
    int m = (blk >> 1) & 3;
    int h = (blk >> 3) & 1;
    int ch = (blk >> 4) % nch;
    int tap = (blk >> 4) / nch;
    int g = lane >> 2, t4 = lane & 3;
    uint32_t regs[4];
    #pragma unroll
    for (int r = 0; r < 4; r++) {
        int co = h * 64 + m * 16 + g + (r & 1) * 8;
        int ci = ch * 32 + k * 16 + t4 * 2 + (r >> 1) * 8;
        __half2 hv = __floats2half2_rn(w[(co * Cin + ci) * 27 + tap],
                                       w[(co * Cin + ci + 1) * 27 + tap]);
        regs[r] = *(uint32_t*)&hv;
    }
    of[idx] = make_uint4(regs[0], regs[1], regs[2], regs[3]);
}

__global__ void wprep2_kernel(const float* __restrict__ w1, const float* __restrict__ w2,
                              uint4* __restrict__ o1, uint4* __restrict__ o2) {
    int t = blockIdx.x * 256 + threadIdx.x;
    if (t < 27648) wprep_one(w1, CIN_, o1, t, 2);
    else if (t < 27648 + 55296) wprep_one(w2, COUT_, o2, t - 27648, 4);
}

// ---------------- scatter (smem transpose -> coalesced atomics) --------------
__global__ void scatter_t_kernel(const float* __restrict__ f,
                                 const int* __restrict__ vox,
                                 float* __restrict__ grid) {
    int b = blockIdx.x >> 6, ng = blockIdx.x & 63;
    int n0 = ng * 64;
    int tid = threadIdx.x;
    __shared__ float buf[64][65];
    #pragma unroll
    for (int k = 0; k < 16; k++) {
        int idx = k * 256 + tid;
        int c = idx >> 6, dn = idx & 63;
        buf[c][dn] = f[((size_t)b * 64 + c) * N_ + n0 + dn];
    }
    __syncthreads();
    #pragma unroll
    for (int k = 0; k < 16; k++) {
        int idx = k * 256 + tid;
        int dn = idx >> 6, c = idx & 63;
        int flat = vox[b * N_ + n0 + dn];
        atomicAdd(&grid[((size_t)b * R3_ + flat) * 64 + c], buf[c][dn]);
    }
}

// ---------------- cleanup (end of run): zero occupied grid cols + cnt --------
__global__ void cleanup_kernel(const int* __restrict__ vox,
                               float* __restrict__ grid, float* __restrict__ cnt) {
    int t = blockIdx.x * 256 + threadIdx.x;   // B*N
    int b = t >> 12;
    int flat = vox[t];
    cnt[b * R3_ + flat] = 0.f;
    float4* g4 = (float4*)&grid[((size_t)b * R3_ + flat) * 64];
    const float4 z = make_float4(0.f, 0.f, 0.f, 0.f);
    #pragma unroll
    for (int k = 0; k < 16; k++) g4[k] = z;
}

// ============================ mma.sync conv3d (fp16) =========================
// CTA: 256 thr = 8 warps. Output tile: [128 co] x [2x2 xy lines x 32 z].
// Direct-LDG W fragments; taps fully unrolled (compile-time addresses).
#define LSTRB   2720
#define FLG_OFF 43520
#define RC_OFF  43584
#define CONV_SMEM 45632

__global__ __launch_bounds__(256, 2)
void conv3d_mma_kernel(const void* __restrict__ in,
                       const uint4* __restrict__ wf,
                       const float* __restrict__ bias,
                       __half* __restrict__ out, int Cin,
                       const float* __restrict__ cnt,
                       const float* __restrict__ gnm, const float* __restrict__ gnrs,
                       const float* __restrict__ gng, const float* __restrict__ gnb,
                       float* __restrict__ gs, float* __restrict__ gs2) {
    extern __shared__ __align__(16) char smem[];
    __half* X = (__half*)smem;
    int* flags = (int*)(smem + FLG_OFF);
    float* rc = (float*)(smem + RC_OFF);
    float* sscale = (float*)(smem + RC_OFF);
    float* sshift = sscale + 32;
    uint32_t sb = smem_u32(smem);
    uint32_t x_u = sb;

    int tid = threadIdx.x, wid = tid >> 5, lane = tid & 31;
    int bx = blockIdx.x, b = blockIdx.y;
    int x0 = (bx >> 4) * 2, y0 = (bx & 15) * 2;
    int nch = Cin >> 5;
    int line = wid & 3;
    int cohalf = wid >> 2;
    int cobase = cohalf * 64;
    int g = lane >> 2, t4 = lane & 3;
    bool hc = (cnt != nullptr);

    uint32_t b_off = ((uint32_t)((lane & 7) + (lane >> 4) * 8) * 40
                      + (uint32_t)((lane >> 3) & 1) * 8) * 2;

    if (tid < 16) flags[tid] = hc ? 0 : 1;
    __syncthreads();
    if (hc) {
        for (int i = tid; i < 512; i += 256) {
            int il = i >> 5, z = i & 31;
            int gx = x0 - 1 + (il >> 2), gy = y0 - 1 + (il & 3);
            float c = 0.f;
            if ((unsigned)gx < 32u && (unsigned)gy < 32u)
                c = cnt[(size_t)b * R3_ + gx * 1024 + gy * 32 + z];
            rc[i] = __frcp_rn(fmaxf(c, 1.f));
            if (c > 0.f) flags[il] = 1;
        }
    }

    float d[4][4][4];
    #pragma unroll
    for (int m = 0; m < 4; m++)
        #pragma unroll
        for (int n = 0; n < 4; n++)
            #pragma unroll
            for (int r = 0; r < 4; r++) d[m][n][r] = 0.f;

    for (int ch = 0; ch < nch; ch++) {
        int c0 = ch * 32;
        __syncthreads();
        if (!hc) {
            if (tid < 32) {
                int cc = c0 + tid;
                int gi = b * NG_ + (cc >> 4);
                float sc = gnrs[gi] * gng[cc];
                sscale[tid] = sc;
                sshift[tid] = gnb[cc] - gnm[gi] * sc;
            }
            __syncthreads();
        }
        for (int i = tid; i < 1024; i += 256) {
            int ci = i & 31, r2 = (i >> 5) & 1, il = i >> 6;
            X[il * 1360 + (r2 ? 33 : 0) * 40 + ci] = __float2half_rn(0.f);
        }
        if (hc) {
            const float* inf = (const float*)in;
            for (int i = tid; i < 4096; i += 256) {
                int c4 = i & 7;
                int z  = (i >> 3) & 31;
                int il = i >> 8;
                int gx = x0 - 1 + (il >> 2), gy = y0 - 1 + (il & 3);
                float4 v = make_float4(0.f, 0.f, 0.f, 0.f);
                if ((unsigned)gx < 32u && (unsigned)gy < 32u)
                    v = *(const float4*)&inf[((size_t)b * R3_ + gx * 1024 + gy * 32 + z) * 64 + c0 + c4 * 4];
                float r = rc[il * 32 + z];
                int base = il * 1360 + (z + 1) * 40 + c4 * 4;
                *(__half2*)&X[base]     = __floats2half2_rn(v.x * r, v.y * r);
                *(__half2*)&X[base + 2] = __floats2half2_rn(v.z * r, v.w * r);
            }
        } else {
            // conv2: fp16 [b][c][voxel]; each thread handles 8 z (uint4 16B)
            const __half* inh = (const __half*)in;
            for (int i = tid; i < 2048; i += 256) {
                int zo = (i & 3) * 8;            // z-octet
                int ci = (i >> 2) & 31;
                int il = i >> 7;
                int gx = x0 - 1 + (il >> 2), gy = y0 - 1 + (il & 3);
                float f[8] = {0.f, 0.f, 0.f, 0.f, 0.f, 0.f, 0.f, 0.f};
                if ((unsigned)gx < 32u && (unsigned)gy < 32u) {
                    uint4 raw = *(const uint4*)&inh[((size_t)(b * Cin + c0 + ci)) * R3_
                                                    + gx * 1024 + gy * 32 + zo];
                    const uint32_t* rp = &raw.x;
                    #pragma unroll
                    for (int q = 0; q < 4; q++) {
                        __half2 h2v = *(__half2*)&rp[q];
                        f[q * 2] = __low2float(h2v);
                        f[q * 2 + 1] = __high2float(h2v);
                    }
                }
                float sc = sscale[ci], sh = sshift[ci];
                int base = il * 1360 + (zo + 1) * 40 + ci;
                #pragma unroll
                for (int j = 0; j < 8; j++)
                    X[base + j * 40] = __float2half_rn(fast_swish(f[j] * sc + sh));
            }
        }
        __syncthreads();

        // taps fully unrolled: all address math compile-time
        const uint4* wchunk = wf + ((size_t)ch * 2 + cohalf) * 8 * 32 + lane;
        const size_t tapstride = (size_t)nch * 2 * 8 * 32;
        #pragma unroll
        for (int dxx = 0; dxx < 3; dxx++) {
            #pragma unroll
            for (int dyy = 0; dyy < 3; dyy++) {
                int il = ((line >> 1) + dxx) * 4 + (line & 1) + dyy;
                int fl = flags[il];
                uint32_t xb0 = x_u + (uint32_t)il * LSTRB + b_off;
                const uint4* wt0 = wchunk + (size_t)(dxx * 9 + dyy * 3) * tapstride;
                #pragma unroll
                for (int dz = 0; dz < 3; dz++) {
                    if (fl) {
                        const uint4* wt = wt0 + (size_t)dz * tapstride;
                        uint32_t xb = xb0 + (uint32_t)dz * 80;
                        uint32_t Bf[2][8];
                        #pragma unroll
                        for (int k = 0; k < 2; k++) {
                            ldsm4(&Bf[k][0], xb + (uint32_t)k * 32);
                            ldsm4(&Bf[k][4], xb + 1280 + (uint32_t)k * 32);
                        }
                        #pragma unroll
                        for (int m = 0; m < 4; m++) {
                            #pragma unroll
                            for (int k = 0; k < 2; k++) {
                                uint4 A = wt[(m * 2 + k) * 32];
                                #pragma unroll
                                for (int n = 0; n < 4; n++)
                                    MMA_F16(d[m][n], A.x, A.y, A.z, A.w,
                                            Bf[k][n * 2], Bf[k][n * 2 + 1]);
                            }
                        }
                    }
                }
            }
        }
    }

    // ---------------- epilogue -------------------------------------------------
    if (hc) {
        int ox = x0 + (line >> 1), oy = y0 + (line & 1);
        #pragma unroll
        for (int m = 0; m < 4; m++) {
            int co = cobase + m * 16 + g;
            float bv0 = bias[co], bv1 = bias[co + 8];
            float s = 0.f, s2 = 0.f;
            __half* p0 = out + ((size_t)(b * COUT_ + co)) * R3_ + ox * 1024 + oy * 32;
            __half* p1 = p0 + (size_t)8 * R3_;
            #pragma unroll
            for (int n = 0; n < 4; n++) {
                float v0 = d[m][n][0] + bv0, v1 = d[m][n][1] + bv0;
                float v2 = d[m][n][2] + bv1, v3 = d[m][n][3] + bv1;
                int z = n * 8 + t4 * 2;
                *(__half2*)(p0 + z) = __floats2half2_rn(v0, v1);
                *(__half2*)(p1 + z) = __floats2half2_rn(v2, v3);
                s += v0 + v1 + v2 + v3;
                s2 += v0 * v0 + v1 * v1 + v2 * v2 + v3 * v3;
            }
            #pragma unroll
            for (int off = 16; off > 0; off >>= 1) {
                s += __shfl_xor_sync(0xffffffffu, s, off);
                s2 += __shfl_xor_sync(0xffffffffu, s2, off);
            }
            if (lane == 0) {
                int grp = b * NG_ + (cobase >> 4) + m;
                atomicAdd(&gs[grp], s);
                atomicAdd(&gs2[grp], s2);
            }
        }
    } else {
        __syncthreads();
        __half* T = (__half*)smem;       // [4 lines][32 z][128 co]
        #pragma unroll
        for (int m = 0; m < 4; m++) {
            int co = cobase + m * 16 + g;
            float bv0 = bias[co], bv1 = bias[co + 8];
            float s = 0.f, s2 = 0.f;
            #pragma unroll
            for (int n = 0; n < 4; n++) {
                float v0 = d[m][n][0] + bv0, v1 = d[m][n][1] + bv0;
                float v2 = d[m][n][2] + bv1, v3 = d[m][n][3] + bv1;
                int z = n * 8 + t4 * 2;
                __half* tb = T + (size_t)line * 4096;
                tb[(z) * 128 + co]     = __float2half_rn(v0);
                tb[(z + 1) * 128 + co] = __float2half_rn(v1);
                tb[(z) * 128 + co + 8]     = __float2half_rn(v2);
                tb[(z + 1) * 128 + co + 8] = __float2half_rn(v3);
                s += v0 + v1 + v2 + v3;
                s2 += v0 * v0 + v1 * v1 + v2 * v2 + v3 * v3;
            }
            #pragma unroll
            for (int off = 16; off > 0; off >>= 1) {
                s += __shfl_xor_sync(0xffffffffu, s, off);
                s2 += __shfl_xor_sync(0xffffffffu, s2, off);
            }
            if (lane == 0) {
                int grp = b * NG_ + (cobase >> 4) + m;
                atomicAdd(&gs[grp], s);
                atomicAdd(&gs2[grp], s2);
            }
        }
        __syncthreads();
        const uint4* Tv = (const uint4*)T;
        for (int i = tid; i < 2048; i += 256) {
            int l = i >> 9, j = i & 511;
            int ox = x0 + (l >> 1), oy = y0 + (l & 1);
            uint4* dst = (uint4*)(out + ((size_t)b * R3_ + ox * 1024 + oy * 32) * 128);
            dst[j] = Tv[i];
        }
    }
}

// ---------------- finalize GN stats (and reset accumulators) -----------------
__global__ void gn_finalize_kernel(float* __restrict__ gs, float* __restrict__ gs2,
                                   float* __restrict__ mean, float* __restrict__ rstd) {
    int i = threadIdx.x;
    const float n = 16.0f * (float)R3_;
    float s = gs[i], s2 = gs2[i];
    float m = s / n;
    mean[i] = m;
    rstd[i] = rsqrtf(s2 / n - m * m + GN_EPS_);
    gs[i] = 0.f; gs2[i] = 0.f;
}

// ---------------- GroupNorm stats (point branch) -----------------------------
__global__ void gn_stats_kernel(const float* __restrict__ x, int S,
                                float* __restrict__ mean, float* __restrict__ rstd) {
    int bg = blockIdx.x;
    const float* p = x + (long)bg * 16 * S;
    int n = 16 * S;
    float s = 0.f, s2 = 0.f;
    for (int i = threadIdx.x; i < n; i += blockDim.x) {
        float v = p[i];
        s += v; s2 += v * v;
    }
    __shared__ float ra[512], rb[512];
    int tid = threadIdx.x;
    ra[tid] = s; rb[tid] = s2; __syncthreads();
    for (int st = 256; st > 0; st >>= 1) {
        if (tid < st) { ra[tid] += ra[tid + st]; rb[tid] += rb[tid + st]; }
        __syncthreads();
    }
    if (tid == 0) {
        float m = ra[0] / (float)n;
        float var = rb[0] / (float)n - m * m;
        mean[bg] = m;
        rstd[bg] = rsqrtf(var + GN_EPS_);
    }
}

__global__ void ptgemm_kernel(const float* __restrict__ f, const float* __restrict__ w,
                              const float* __restrict__ bias, float* __restrict__ pf) {
    int t = blockIdx.x * blockDim.x + threadIdx.x;
    int n = t & (N_ - 1);
    int r = t >> 12;
    int o = (r & 31) * 4;
    int b = r >> 5;
    float a0 = bias[o], a1 = bias[o + 1], a2 = bias[o + 2], a3 = bias[o + 3];
    const float* fb = f + (b * CIN_) * N_ + n;
    const float* w0 = w + o * CIN_;
    #pragma unroll 8
    for (int c = 0; c < CIN_; c++) {
        float fv = fb[c * N_];
        a0 += w0[c] * fv;
        a1 += w0[CIN_ + c] * fv;
        a2 += w0[2 * CIN_ + c] * fv;
        a3 += w0[3 * CIN_ + c] * fv;
    }
    float* op = &pf[(b * COUT_ + o) * N_ + n];
    op[0] = a0; op[N_] = a1; op[2 * N_] = a2; op[3 * N_] = a3;
}

// -------- devoxelize (fp16 channel-last h2, fused GN+swish) + point branch ---
__global__ void final_kernel(const float* __restrict__ nc, const __half* __restrict__ h2,
                             const float* __restrict__ pf,
                             const float* __restrict__ g2g, const float* __restrict__ g2b,
                             const float* __restrict__ mean2, const float* __restrict__ rstd2,
                             const float* __restrict__ pgg, const float* __restrict__ pgb,
                             const float* __restrict__ meanp, const float* __restrict__ rstdp,
                             float* __restrict__ out) {
    int t = blockIdx.x * blockDim.x + threadIdx.x;
    int n = t & (N_ - 1);
    int r = t >> 12;
    int o = (r & 31) * 4;
    int b = r >> 5;

    float ncx = nc[(b * N_ + n) * 3 + 0];
    float ncy = nc[(b * N_ + n) * 3 + 1];
    float ncz = nc[(b * N_ + n) * 3 + 2];
    float fx = floorf(ncx), fy = floorf(ncy), fz = floorf(ncz);
    float dx = ncx - fx, dy = ncy - fy, dz = ncz - fz;
    int ix0 = (int)fx, iy0 = (int)fy, iz0 = (int)fz;
    int ix1 = min(ix0 + 1, R_ - 1), iy1 = min(iy0 + 1, R_ - 1), iz1 = min(iz0 + 1, R_ - 1);
    float wx[2] = {1.f - dx, dx}, wy[2] = {1.f - dy, dy}, wz[2] = {1.f - dz, dz};
    int xs[2] = {ix0, ix1}, ys[2] = {iy0, iy1}, zs[2] = {iz0, iz1};

    int gidx = b * NG_ + (o >> 4);
    float m2 = mean2[gidx], rs2 = rstd2[gidx];
    float ga[4], be[4];
    #pragma unroll
    for (int j = 0; j < 4; j++) { ga[j] = g2g[o + j]; be[j] = g2b[o + j]; }

    float dv[4] = {0.f, 0.f, 0.f, 0.f};
    const __half* hb = h2 + ((size_t)b * R3_) * 128;
    #pragma unroll
    for (int k = 0; k < 8; k++) {
        int kx = k >> 2, ky = (k >> 1) & 1, kz = k & 1;
        float wk = wx[kx] * wy[ky] * wz[kz];
        int id = (xs[kx] * R_ + ys[ky]) * R_ + zs[kz];
        uint2 raw = *(const uint2*)&hb[(size_t)id * 128 + o];
        __half2 a01 = *(__half2*)&raw.x, a23 = *(__half2*)&raw.y;
        float hv[4] = {__low2float(a01), __high2float(a01),
                       __low2float(a23), __high2float(a23)};
        #pragma unroll
        for (int j = 0; j < 4; j++) {
            float y = (hv[j] - m2) * rs2 * ga[j] + be[j];
            dv[j] += wk * fast_swish(y);
        }
    }

    float mp = meanp[gidx], rsp = rstdp[gidx];
    const float* pp = &pf[(b * COUT_ + o) * N_ + n];
    float* op = &out[(b * COUT_ + o) * N_ + n];
    #pragma unroll
    for (int j = 0; j < 4; j++) {
        int c = o + j;
        float y = (pp[j * N_] - mp) * rsp * pgg[c] + pgb[c];
        op[j * N_] = dv[j] + fast_swish(y);
    }
}

// ---------------- host launcher ----------------------------------------------
extern "C" void kernel_launch(void* const* d_in, const int* in_sizes, int n_in,
                              void* d_out, int out_size) {
    const float* features = (const float*)d_in[0];
    const float* coords   = (const float*)d_in[1];
    const float* c1w = (const float*)d_in[2];
    const float* c1b = (const float*)d_in[3];
    const float* g1g = (const float*)d_in[4];
    const float* g1b = (const float*)d_in[5];
    const float* c2w = (const float*)d_in[6];
    const float* c2b = (const float*)d_in[7];
    const float* g2g = (const float*)d_in[8];
    const float* g2b = (const float*)d_in[9];
    const float* ptw = (const float*)d_in[10];
    const float* ptb = (const float*)d_in[11];
    const float* pgg = (const float*)d_in[12];
    const float* pgb = (const float*)d_in[13];
    float* out = (float*)d_out;

    float *grid_p, *cnt_p, *pf, *nc;
    float *mean_p, *rstd_p, *mean2_p, *rstd2_p, *gs, *gs2;
    __half *h1, *h2;
    int* vox_p;
    uint4 *w1f, *w2f;
    cudaGetSymbolAddress((void**)&grid_p, g_grid);
    cudaGetSymbolAddress((void**)&cnt_p, g_cnt);
    cudaGetSymbolAddress((void**)&vox_p, g_vox);
    cudaGetSymbolAddress((void**)&nc, g_nc);
    cudaGetSymbolAddress((void**)&h1, g_h1);
    cudaGetSymbolAddress((void**)&h2, g_h2);
    cudaGetSymbolAddress((void**)&pf, g_pf);
    cudaGetSymbolAddress((void**)&mean_p, g_mean);
    cudaGetSymbolAddress((void**)&rstd_p, g_rstd);
    cudaGetSymbolAddress((void**)&mean2_p, g_mean2);
    cudaGetSymbolAddress((void**)&rstd2_p, g_rstd2);
    cudaGetSymbolAddress((void**)&gs, g_sum);
    cudaGetSymbolAddress((void**)&gs2, g_sum2);
    cudaGetSymbolAddress((void**)&w1f, g_w1f);
    cudaGetSymbolAddress((void**)&w2f, g_w2f);

    cudaFuncSetAttribute(conv3d_mma_kernel,
                         cudaFuncAttributeMaxDynamicSharedMemorySize, CONV_SMEM);

    coords_kernel<<<B_, 256>>>(coords, nc, vox_p, cnt_p);                              // 1
    wprep2_kernel<<<(27648 + 55296 + 255) / 256, 256>>>(c1w, c2w, w1f, w2f);           // 2
    scatter_t_kernel<<<B_ * 64, 256>>>(features, vox_p, grid_p);                       // 3
    conv3d_mma_kernel<<<dim3(256, 8), 256, CONV_SMEM>>>(grid_p, w1f, c1b, h1, CIN_,
        cnt_p, nullptr, nullptr, nullptr, nullptr, gs, gs2);                           // 4 <- ncu
    gn_finalize_kernel<<<1, B_ * NG_>>>(gs, gs2, mean_p, rstd_p);                      // 5
    conv3d_mma_kernel<<<dim3(256, 8), 256, CONV_SMEM>>>(h1, w2f, c2b, h2, COUT_,
        nullptr, mean_p, rstd_p, g1g, g1b, gs, gs2);                                   // 6
    gn_finalize_kernel<<<1, B_ * NG_>>>(gs, gs2, mean2_p, rstd2_p);                    // 7
    ptgemm_kernel<<<4096, 256>>>(features, ptw, ptb, pf);                              // 8
    gn_stats_kernel<<<B_ * NG_, 512>>>(pf, N_, mean_p, rstd_p);                        // 9
    final_kernel<<<4096, 256>>>(nc, h2, pf, g2g, g2b, mean2_p, rstd2_p,
                                pgg, pgb, mean_p, rstd_p, out);                        // 10
    cleanup_kernel<<<B_ * N_ / 256, 256>>>(vox_p, grid_p, cnt_p);                      // 11
}

// round 15
// speedup vs baseline: 1.7973x; 1.0476x over previous
#include <cuda_runtime.h>
#include <cuda_fp16.h>
#include <math.h>
#include <stdint.h>

#define B_    8
#define N_    4096
#define CIN_  64
#define COUT_ 128
#define R_    32
#define R3_   32768
#define NG_   8
#define GN_EPS_ 1e-5f

// ---------------- scratch (static device globals; no allocation) -------------
static __device__ float  g_grid[B_ * R3_ * CIN_];    // [b][voxel][ci]
static __device__ float  g_cnt [B_ * R3_];
static __device__ int    g_vox [B_ * N_];
static __device__ float  g_nc  [B_ * N_ * 3];
static __device__ __half g_h1  [B_ * COUT_ * R3_];   // fp16, channel-major
static __device__ __half g_h2  [B_ * R3_ * COUT_];   // fp16, channel-LAST
static __device__ float  g_pf  [B_ * COUT_ * N_];
static __device__ float  g_mean [B_ * NG_];
static __device__ float  g_rstd [B_ * NG_];
static __device__ float  g_mean2[B_ * NG_];
static __device__ float  g_rstd2[B_ * NG_];
static __device__ float  g_sum [B_ * NG_];
static __device__ float  g_sum2[B_ * NG_];
// W in mma A-fragment layout: [tap][chunk][cohalf][m 4][k 2][lane 32] x uint4
static __device__ uint4 g_w1f[27648];
static __device__ uint4 g_w2f[55296];
static __device__ float g_ptwT[CIN_ * COUT_];        // pt_w transposed [ci][co]

// ---------------- mma.sync m16n8k16 fp16 ------------------------------------
#define MMA_F16(dd, a0, a1, a2, a3, b0, b1) \
    asm volatile("mma.sync.aligned.m16n8k16.row.col.f32.f16.f16.f32 " \
        "{%0,%1,%2,%3}, {%4,%5,%6,%7}, {%8,%9}, {%0,%1,%2,%3};" \
        : "+f"((dd)[0]), "+f"((dd)[1]), "+f"((dd)[2]), "+f"((dd)[3]) \
        : "r"(a0), "r"(a1), "r"(a2), "r"(a3), "r"(b0), "r"(b1))

__device__ __forceinline__ void ldsm4(uint32_t* r, uint32_t addr) {
    asm volatile("ldmatrix.sync.aligned.m8n8.x4.shared.b16 {%0,%1,%2,%3}, [%4];"
        : "=r"(r[0]), "=r"(r[1]), "=r"(r[2]), "=r"(r[3]) : "r"(addr));
}
__device__ __forceinline__ uint32_t smem_u32(const void* p) {
    uint32_t a;
    asm("{ .reg .u64 t; cvta.to.shared.u64 t, %1; cvt.u32.u64 %0, t; }" : "=r"(a) : "l"(p));
    return a;
}
__device__ __forceinline__ float fast_swish(float y) {
    return y / (1.0f + __expf(-y));
}

// ============================ coords ==========================================
__global__ void coords_kernel(const float* __restrict__ coords,
                              float* __restrict__ nc, int* __restrict__ vox,
                              float* __restrict__ cnt) {
    int b = blockIdx.x, tid = threadIdx.x;
    __shared__ float red[256];
    __shared__ float smean[3];
    __shared__ float sinv;

    float s0 = 0.f, s1 = 0.f, s2 = 0.f;
    for (int n = tid; n < N_; n += 256) {
        const float* c = &coords[(b * N_ + n) * 3];
        s0 += c[0]; s1 += c[1]; s2 += c[2];
    }
    float ss[3] = {s0, s1, s2};
    for (int d = 0; d < 3; d++) {
        red[tid] = ss[d]; __syncthreads();
        for (int st = 128; st > 0; st >>= 1) {
            if (tid < st) red[tid] += red[tid + st];
            __syncthreads();
        }
        if (tid == 0) smean[d] = red[0] * (1.0f / N_);
        __syncthreads();
    }
    float m0 = smean[0], m1 = smean[1], m2 = smean[2];

    float mx = 0.f;
    for (int n = tid; n < N_; n += 256) {
        const float* c = &coords[(b * N_ + n) * 3];
        float dx = c[0] - m0, dy = c[1] - m1, dz = c[2] - m2;
        mx = fmaxf(mx, dx * dx + dy * dy + dz * dz);
    }
    red[tid] = mx; __syncthreads();
    for (int st = 128; st > 0; st >>= 1) {
        if (tid < st) red[tid] = fmaxf(red[tid], red[tid + st]);
        __syncthreads();
    }
    if (tid == 0) sinv = 1.0f / (2.0f * sqrtf(red[0]));
    __syncthreads();
    float inv = sinv;

    for (int n = tid; n < N_; n += 256) {
        const float* c = &coords[(b * N_ + n) * 3];
        float v[3]; int iv[3];
        float cc[3] = {c[0] - m0, c[1] - m1, c[2] - m2};
        #pragma unroll
        for (int d = 0; d < 3; d++) {
            float x = (cc[d] * inv + 0.5f) * (float)R_;
            x = fminf(fmaxf(x, 0.f), (float)(R_ - 1));
            v[d] = x;
            iv[d] = (int)rintf(x);
        }
        nc[(b * N_ + n) * 3 + 0] = v[0];
        nc[(b * N_ + n) * 3 + 1] = v[1];
        nc[(b * N_ + n) * 3 + 2] = v[2];
        int flat = (iv[0] * R_ + iv[1]) * R_ + iv[2];
        vox[b * N_ + n] = flat;
        atomicAdd(&cnt[b * R3_ + flat], 1.0f);
    }
}

// ---------------- weight prep: conv fragments + ptw transpose ----------------
__device__ __forceinline__ void wprep_one(const float* __restrict__ w, int Cin,
                                          uint4* __restrict__ of, int idx, int nch) {
    int lane = idx & 31;
    int blk = idx >> 5;
    int k = blk & 1;
    int m = (blk >> 1) & 3;
    int h = (blk >> 3) & 1;
    int ch = (blk >> 4) % nch;
    int tap = (blk >> 4) / nch;
    int g = lane >> 2, t4 = lane & 3;
    uint32_t regs[4];
    #pragma unroll
    for (int r = 0; r < 4; r++) {
        int co = h * 64 + m * 16 + g + (r & 1) * 8;
        int ci = ch * 32 + k * 16 + t4 * 2 + (r >> 1) * 8;
        __half2 hv = __floats2half2_rn(w[(co * Cin + ci) * 27 + tap],
                                       w[(co * Cin + ci + 1) * 27 + tap]);
        regs[r] = *(uint32_t*)&hv;
    }
    of[idx] = make_uint4(regs[0], regs[1], regs[2], regs[3]);
}

__global__ void wprep2_kernel(const float* __restrict__ w1, const float* __restrict__ w2,
                              const float* __restrict__ ptw,
                              uint4* __restrict__ o1, uint4* __restrict__ o2,
                              float* __restrict__ wT) {
    int t = blockIdx.x * 256 + threadIdx.x;
    if (t < 27648) wprep_one(w1, CIN_, o1, t, 2);
    else if (t < 27648 + 55296) wprep_one(w2, COUT_, o2, t - 27648, 4);
    else if (t < 27648 + 55296 + 8192) {
        int i = t - (27648 + 55296);
        int co = i >> 6, ci = i & 63;
        wT[ci * COUT_ + co] = ptw[co * CIN_ + ci];
    }
}

// ---------------- scatter (smem transpose -> coalesced atomics) --------------
__global__ void scatter_t_kernel(const float* __restrict__ f,
                                 const int* __restrict__ vox,
                                 float* __restrict__ grid) {
    int b = blockIdx.x >> 6, ng = blockIdx.x & 63;
    int n0 = ng * 64;
    int tid = threadIdx.x;
    __shared__ float buf[64][65];
    #pragma unroll
    for (int k = 0; k < 16; k++) {
        int idx = k * 256 + tid;
        int c = idx >> 6, dn = idx & 63;
        buf[c][dn] = f[((size_t)b * 64 + c) * N_ + n0 + dn];
    }
    __syncthreads();
    #pragma unroll
    for (int k = 0; k < 16; k++) {
        int idx = k * 256 + tid;
        int dn = idx >> 6, c = idx & 63;
        int flat = vox[b * N_ + n0 + dn];
        atomicAdd(&grid[((size_t)b * R3_ + flat) * 64 + c], buf[c][dn]);
    }
}

// ---------------- cleanup (end of run): zero occupied grid cols + cnt --------
__global__ void cleanup_kernel(const int* __restrict__ vox,
                               float* __restrict__ grid, float* __restrict__ cnt) {
    int t = blockIdx.x * 256 + threadIdx.x;   // B*N
    int b = t >> 12;
    int flat = vox[t];
    cnt[b * R3_ + flat] = 0.f;
    float4* g4 = (float4*)&grid[((size_t)b * R3_ + flat) * 64];
    const float4 z = make_float4(0.f, 0.f, 0.f, 0.f);
    #pragma unroll
    for (int k = 0; k < 16; k++) g4[k] = z;
}

// ============================ mma.sync conv3d (fp16) =========================
#define LSTRB   2720
#define FLG_OFF 43520
#define RC_OFF  43584
#define CONV_SMEM 45632

__global__ __launch_bounds__(256, 2)
void conv3d_mma_kernel(const void* __restrict__ in,
                       const uint4* __restrict__ wf,
                       const float* __restrict__ bias,
                       __half* __restrict__ out, int Cin,
                       const float* __restrict__ cnt,
                       const float* __restrict__ gnm, const float* __restrict__ gnrs,
                       const float* __restrict__ gng, const float* __restrict__ gnb,
                       float* __restrict__ gs, float* __restrict__ gs2) {
    extern __shared__ __align__(16) char smem[];
    __half* X = (__half*)smem;
    int* flags = (int*)(smem + FLG_OFF);
    float* rc = (float*)(smem + RC_OFF);
    float* sscale = (float*)(smem + RC_OFF);
    float* sshift = sscale + 32;
    uint32_t sb = smem_u32(smem);
    uint32_t x_u = sb;

    int tid = threadIdx.x, wid = tid >> 5, lane = tid & 31;
    int bx = blockIdx.x, b = blockIdx.y;
    int x0 = (bx >> 4) * 2, y0 = (bx & 15) * 2;
    int nch = Cin >> 5;
    int line = wid & 3;
    int cohalf = wid >> 2;
    int cobase = cohalf * 64;
    int g = lane >> 2, t4 = lane & 3;
    bool hc = (cnt != nullptr);

    uint32_t b_off = ((uint32_t)((lane & 7) + (lane >> 4) * 8) * 40
                      + (uint32_t)((lane >> 3) & 1) * 8) * 2;

    if (tid < 16) flags[tid] = hc ? 0 : 1;
    __syncthreads();
    if (hc) {
        for (int i = tid; i < 512; i += 256) {
            int il = i >> 5, z = i & 31;
            int gx = x0 - 1 + (il >> 2), gy = y0 - 1 + (il & 3);
            float c = 0.f;
            if ((unsigned)gx < 32u && (unsigned)gy < 32u)
                c = cnt[(size_t)b * R3_ + gx * 1024 + gy * 32 + z];
            rc[i] = __frcp_rn(fmaxf(c, 1.f));
            if (c > 0.f) flags[il] = 1;
        }
    }

    float d[4][4][4];
    #pragma unroll
    for (int m = 0; m < 4; m++)
        #pragma unroll
        for (int n = 0; n < 4; n++)
            #pragma unroll
            for (int r = 0; r < 4; r++) d[m][n][r] = 0.f;

    for (int ch = 0; ch < nch; ch++) {
        int c0 = ch * 32;
        __syncthreads();
        if (!hc) {
            if (tid < 32) {
                int cc = c0 + tid;
                int gi = b * NG_ + (cc >> 4);
                float sc = gnrs[gi] * gng[cc];
                sscale[tid] = sc;
                sshift[tid] = gnb[cc] - gnm[gi] * sc;
            }
            __syncthreads();
        }
        for (int i = tid; i < 1024; i += 256) {
            int ci = i & 31, r2 = (i >> 5) & 1, il = i >> 6;
            X[il * 1360 + (r2 ? 33 : 0) * 40 + ci] = __float2half_rn(0.f);
        }
        if (hc) {
            const float* inf = (const float*)in;
            for (int i = tid; i < 4096; i += 256) {
                int c4 = i & 7;
                int z  = (i >> 3) & 31;
                int il = i >> 8;
                int gx = x0 - 1 + (il >> 2), gy = y0 - 1 + (il & 3);
                float4 v = make_float4(0.f, 0.f, 0.f, 0.f);
                if ((unsigned)gx < 32u && (unsigned)gy < 32u)
                    v = *(const float4*)&inf[((size_t)b * R3_ + gx * 1024 + gy * 32 + z) * 64 + c0 + c4 * 4];
                float r = rc[il * 32 + z];
                int base = il * 1360 + (z + 1) * 40 + c4 * 4;
                *(__half2*)&X[base]     = __floats2half2_rn(v.x * r, v.y * r);
                *(__half2*)&X[base + 2] = __floats2half2_rn(v.z * r, v.w * r);
            }
        } else {
            const __half* inh = (const __half*)in;
            for (int i = tid; i < 2048; i += 256) {
                int zo = (i & 3) * 8;
                int ci = (i >> 2) & 31;
                int il = i >> 7;
                int gx = x0 - 1 + (il >> 2), gy = y0 - 1 + (il & 3);
                float f[8] = {0.f, 0.f, 0.f, 0.f, 0.f, 0.f, 0.f, 0.f};
                if ((unsigned)gx < 32u && (unsigned)gy < 32u) {
                    uint4 raw = *(const uint4*)&inh[((size_t)(b * Cin + c0 + ci)) * R3_
                                                    + gx * 1024 + gy * 32 + zo];
                    const uint32_t* rp = &raw.x;
                    #pragma unroll
                    for (int q = 0; q < 4; q++) {
                        __half2 h2v = *(__half2*)&rp[q];
                        f[q * 2] = __low2float(h2v);
                        f[q * 2 + 1] = __high2float(h2v);
                    }
                }
                float sc = sscale[ci], sh = sshift[ci];
                int base = il * 1360 + (zo + 1) * 40 + ci;
                #pragma unroll
                for (int j = 0; j < 8; j++)
                    X[base + j * 40] = __float2half_rn(fast_swish(f[j] * sc + sh));
            }
        }
        __syncthreads();

        // taps fully unrolled; A fragments batch-loaded per tap (MLP=8)
        const uint4* wchunk = wf + ((size_t)ch * 2 + cohalf) * 8 * 32 + lane;
        const size_t tapstride = (size_t)nch * 2 * 8 * 32;
        #pragma unroll
        for (int dxx = 0; dxx < 3; dxx++) {
            #pragma unroll
            for (int dyy = 0; dyy < 3; dyy++) {
                int il = ((line >> 1) + dxx) * 4 + (line & 1) + dyy;
                int fl = flags[il];
                uint32_t xb0 = x_u + (uint32_t)il * LSTRB + b_off;
                const uint4* wt0 = wchunk + (size_t)(dxx * 9 + dyy * 3) * tapstride;
                #pragma unroll
                for (int dz = 0; dz < 3; dz++) {
                    if (fl) {
                        const uint4* wt = wt0 + (size_t)dz * tapstride;
                        uint4 A[8];
                        #pragma unroll
                        for (int mk = 0; mk < 8; mk++) A[mk] = wt[mk * 32];
                        uint32_t xb = xb0 + (uint32_t)dz * 80;
                        uint32_t Bf[2][8];
                        #pragma unroll
                        for (int k = 0; k < 2; k++) {
                            ldsm4(&Bf[k][0], xb + (uint32_t)k * 32);
                            ldsm4(&Bf[k][4], xb + 1280 + (uint32_t)k * 32);
                        }
                        #pragma unroll
                        for (int m = 0; m < 4; m++) {
                            #pragma unroll
                            for (int k = 0; k < 2; k++) {
                                const uint4& Av = A[m * 2 + k];
                                #pragma unroll
                                for (int n = 0; n < 4; n++)
                                    MMA_F16(d[m][n], Av.x, Av.y, Av.z, Av.w,
                                            Bf[k][n * 2], Bf[k][n * 2 + 1]);
                            }
                        }
                    }
                }
            }
        }
    }

    // ---------------- epilogue -------------------------------------------------
    if (hc) {
        int ox = x0 + (line >> 1), oy = y0 + (line & 1);
        #pragma unroll
        for (int m = 0; m < 4; m++) {
            int co = cobase + m * 16 + g;
            float bv0 = bias[co], bv1 = bias[co + 8];
            float s = 0.f, s2 = 0.f;
            __half* p0 = out + ((size_t)(b * COUT_ + co)) * R3_ + ox * 1024 + oy * 32;
            __half* p1 = p0 + (size_t)8 * R3_;
            #pragma unroll
            for (int n = 0; n < 4; n++) {
                float v0 = d[m][n][0] + bv0, v1 = d[m][n][1] + bv0;
                float v2 = d[m][n][2] + bv1, v3 = d[m][n][3] + bv1;
                int z = n * 8 + t4 * 2;
                *(__half2*)(p0 + z) = __floats2half2_rn(v0, v1);
                *(__half2*)(p1 + z) = __floats2half2_rn(v2, v3);
                s += v0 + v1 + v2 + v3;
                s2 += v0 * v0 + v1 * v1 + v2 * v2 + v3 * v3;
            }
            #pragma unroll
            for (int off = 16; off > 0; off >>= 1) {
                s += __shfl_xor_sync(0xffffffffu, s, off);
                s2 += __shfl_xor_sync(0xffffffffu, s2, off);
            }
            if (lane == 0) {
                int grp = b * NG_ + (cobase >> 4) + m;
                atomicAdd(&gs[grp], s);
                atomicAdd(&gs2[grp], s2);
            }
        }
    } else {
        __syncthreads();
        __half* T = (__half*)smem;       // [4 lines][32 z][128 co]
        #pragma unroll
        for (int m = 0; m < 4; m++) {
            int co = cobase + m * 16 + g;
            float bv0 = bias[co], bv1 = bias[co + 8];
            float s = 0.f, s2 = 0.f;
            #pragma unroll
            for (int n = 0; n < 4; n++) {
                float v0 = d[m][n][0] + bv0, v1 = d[m][n][1] + bv0;
                float v2 = d[m][n][2] + bv1, v3 = d[m][n][3] + bv1;
                int z = n * 8 + t4 * 2;
                __half* tb = T + (size_t)line * 4096;
                tb[(z) * 128 + co]     = __float2half_rn(v0);
                tb[(z + 1) * 128 + co] = __float2half_rn(v1);
                tb[(z) * 128 + co + 8]     = __float2half_rn(v2);
                tb[(z + 1) * 128 + co + 8] = __float2half_rn(v3);
                s += v0 + v1 + v2 + v3;
                s2 += v0 * v0 + v1 * v1 + v2 * v2 + v3 * v3;
            }
            #pragma unroll
            for (int off = 16; off > 0; off >>= 1) {
                s += __shfl_xor_sync(0xffffffffu, s, off);
                s2 += __shfl_xor_sync(0xffffffffu, s2, off);
            }
            if (lane == 0) {
                int grp = b * NG_ + (cobase >> 4) + m;
                atomicAdd(&gs[grp], s);
                atomicAdd(&gs2[grp], s2);
            }
        }
        __syncthreads();
        const uint4* Tv = (const uint4*)T;
        for (int i = tid; i < 2048; i += 256) {
            int l = i >> 9, j = i & 511;
            int ox = x0 + (l >> 1), oy = y0 + (l & 1);
            uint4* dst = (uint4*)(out + ((size_t)b * R3_ + ox * 1024 + oy * 32) * 128);
            dst[j] = Tv[i];
        }
    }
}

// ---------------- finalize GN stats (count-parameterized) ---------------------
__global__ void gn_finalize_kernel(float* __restrict__ gs, float* __restrict__ gs2,
                                   float* __restrict__ mean, float* __restrict__ rstd,
                                   float n) {
    int i = threadIdx.x;
    float s = gs[i], s2 = gs2[i];
    float m = s / n;
    mean[i] = m;
    rstd[i] = rsqrtf(s2 / n - m * m + GN_EPS_);
    gs[i] = 0.f; gs2[i] = 0.f;
}

// ---------------- tiled point GEMM + fused GN stats ---------------------------
// block (b, nb): 64-n tile, all 128 co. smem: sF[64ci][64n] + sW[64ci][129co].
#define PT_SMEM (64 * 64 * 4 + 64 * 129 * 4)
__global__ __launch_bounds__(256)
void ptgemm_kernel(const float* __restrict__ f, const float* __restrict__ wT,
                   const float* __restrict__ bias, float* __restrict__ pf,
                   float* __restrict__ gs, float* __restrict__ gs2) {
    extern __shared__ float ps[];
    float* sF = ps;              // [64][64]
    float* sW = ps + 4096;       // [64][129]
    int bidx = blockIdx.x;
    int b = bidx >> 6, n0 = (bidx & 63) * 64;
    int tid = threadIdx.x;

    for (int i = tid; i < 4096; i += 256) {
        int ci = i >> 6, n = i & 63;
        sF[ci * 64 + n] = f[((size_t)b * 64 + ci) * N_ + n0 + n];
    }
    for (int i = tid; i < 8192; i += 256) {
        int ci = i >> 7, co = i & 127;
        sW[ci * 129 + co] = wT[ci * COUT_ + co];
    }
    __syncthreads();

    int co = tid & 127, ng = tid >> 7;   // ng = 0/1 -> n-half
    float acc[32];
    float bv = bias[co];
    #pragma unroll
    for (int j = 0; j < 32; j++) acc[j] = bv;
    for (int ci = 0; ci < 64; ci++) {
        float wv = sW[ci * 129 + co];
        const float* fr = sF + ci * 64 + ng * 32;
        #pragma unroll
        for (int j = 0; j < 32; j++) acc[j] += wv * fr[j];
    }
    float* op = &pf[((size_t)b * COUT_ + co) * N_ + n0 + ng * 32];
    float s = 0.f, s2 = 0.f;
    #pragma unroll
    for (int j = 0; j < 32; j++) {
        op[j] = acc[j];
        s += acc[j]; s2 += acc[j] * acc[j];
    }
    // segmented 16-lane reduce (lanes 0-15 = one GN group, 16-31 = next)
    #pragma unroll
    for (int off = 8; off > 0; off >>= 1) {
        s += __shfl_down_sync(0xffffffffu, s, off);
        s2 += __shfl_down_sync(0xffffffffu, s2, off);
    }
    if ((tid & 15) == 0) {
        int grp = b * NG_ + (co >> 4);
        atomicAdd(&gs[grp], s);
        atomicAdd(&gs2[grp], s2);
    }
}

// -------- devoxelize (fp16 channel-last h2, fused GN+swish) + point branch ---
__global__ void final_kernel(const float* __restrict__ nc, const __half* __restrict__ h2,
                             const float* __restrict__ pf,
                             const float* __restrict__ g2g, const float* __restrict__ g2b,
                             const float* __restrict__ mean2, const float* __restrict__ rstd2,
                             const float* __restrict__ pgg, const float* __restrict__ pgb,
                             const float* __restrict__ meanp, const float* __restrict__ rstdp,
                             float* __restrict__ out) {
    int t = blockIdx.x * blockDim.x + threadIdx.x;
    int n = t & (N_ - 1);
    int r = t >> 12;
    int o = (r & 31) * 4;
    int b = r >> 5;

    float ncx = nc[(b * N_ + n) * 3 + 0];
    float ncy = nc[(b * N_ + n) * 3 + 1];
    float ncz = nc[(b * N_ + n) * 3 + 2];
    float fx = floorf(ncx), fy = floorf(ncy), fz = floorf(ncz);
    float dx = ncx - fx, dy = ncy - fy, dz = ncz - fz;
    int ix0 = (int)fx, iy0 = (int)fy, iz0 = (int)fz;
    int ix1 = min(ix0 + 1, R_ - 1), iy1 = min(iy0 + 1, R_ - 1), iz1 = min(iz0 + 1, R_ - 1);
    float wx[2] = {1.f - dx, dx}, wy[2] = {1.f - dy, dy}, wz[2] = {1.f - dz, dz};
    int xs[2] = {ix0, ix1}, ys[2] = {iy0, iy1}, zs[2] = {iz0, iz1};

    int gidx = b * NG_ + (o >> 4);
    float m2 = mean2[gidx], rs2 = rstd2[gidx];
    float ga[4], be[4];
    #pragma unroll
    for (int j = 0; j < 4; j++) { ga[j] = g2g[o + j]; be[j] = g2b[o + j]; }

    float dv[4] = {0.f, 0.f, 0.f, 0.f};
    const __half* hb = h2 + ((size_t)b * R3_) * 128;
    #pragma unroll
    for (int k = 0; k < 8; k++) {
        int kx = k >> 2, ky = (k >> 1) & 1, kz = k & 1;
        float wk = wx[kx] * wy[ky] * wz[kz];
        int id = (xs[kx] * R_ + ys[ky]) * R_ + zs[kz];
        uint2 raw = *(const uint2*)&hb[(size_t)id * 128 + o];
        __half2 a01 = *(__half2*)&raw.x, a23 = *(__half2*)&raw.y;
        float hv[4] = {__low2float(a01), __high2float(a01),
                       __low2float(a23), __high2float(a23)};
        #pragma unroll
        for (int j = 0; j < 4; j++) {
            float y = (hv[j] - m2) * rs2 * ga[j] + be[j];
            dv[j] += wk * fast_swish(y);
        }
    }

    float mp = meanp[gidx], rsp = rstdp[gidx];
    const float* pp = &pf[(b * COUT_ + o) * N_ + n];
    float* op = &out[(b * COUT_ + o) * N_ + n];
    #pragma unroll
    for (int j = 0; j < 4; j++) {
        int c = o + j;
        float y = (pp[j * N_] - mp) * rsp * pgg[c] + pgb[c];
        op[j * N_] = dv[j] + fast_swish(y);
    }
}

// ---------------- host launcher ----------------------------------------------
extern "C" void kernel_launch(void* const* d_in, const int* in_sizes, int n_in,
                              void* d_out, int out_size) {
    const float* features = (const float*)d_in[0];
    const float* coords   = (const float*)d_in[1];
    const float* c1w = (const float*)d_in[2];
    const float* c1b = (const float*)d_in[3];
    const float* g1g = (const float*)d_in[4];
    const float* g1b = (const float*)d_in[5];
    const float* c2w = (const float*)d_in[6];
    const float* c2b = (const float*)d_in[7];
    const float* g2g = (const float*)d_in[8];
    const float* g2b = (const float*)d_in[9];
    const float* ptw = (const float*)d_in[10];
    const float* ptb = (const float*)d_in[11];
    const float* pgg = (const float*)d_in[12];
    const float* pgb = (const float*)d_in[13];
    float* out = (float*)d_out;

    float *grid_p, *cnt_p, *pf, *nc, *ptwT;
    float *mean_p, *rstd_p, *mean2_p, *rstd2_p, *gs, *gs2;
    __half *h1, *h2;
    int* vox_p;
    uint4 *w1f, *w2f;
    cudaGetSymbolAddress((void**)&grid_p, g_grid);
    cudaGetSymbolAddress((void**)&cnt_p, g_cnt);
    cudaGetSymbolAddress((void**)&vox_p, g_vox);
    cudaGetSymbolAddress((void**)&nc, g_nc);
    cudaGetSymbolAddress((void**)&h1, g_h1);
    cudaGetSymbolAddress((void**)&h2, g_h2);
    cudaGetSymbolAddress((void**)&pf, g_pf);
    cudaGetSymbolAddress((void**)&mean_p, g_mean);
    cudaGetSymbolAddress((void**)&rstd_p, g_rstd);
    cudaGetSymbolAddress((void**)&mean2_p, g_mean2);
    cudaGetSymbolAddress((void**)&rstd2_p, g_rstd2);
    cudaGetSymbolAddress((void**)&gs, g_sum);
    cudaGetSymbolAddress((void**)&gs2, g_sum2);
    cudaGetSymbolAddress((void**)&w1f, g_w1f);
    cudaGetSymbolAddress((void**)&w2f, g_w2f);
    cudaGetSymbolAddress((void**)&ptwT, g_ptwT);

    cudaFuncSetAttribute(conv3d_mma_kernel,
                         cudaFuncAttributeMaxDynamicSharedMemorySize, CONV_SMEM);
    cudaFuncSetAttribute(ptgemm_kernel,
                         cudaFuncAttributeMaxDynamicSharedMemorySize, PT_SMEM);

    coords_kernel<<<B_, 256>>>(coords, nc, vox_p, cnt_p);                              // 1
    wprep2_kernel<<<(27648 + 55296 + 8192 + 255) / 256, 256>>>(c1w, c2w, ptw,
                                                               w1f, w2f, ptwT);        // 2
    scatter_t_kernel<<<B_ * 64, 256>>>(features, vox_p, grid_p);                       // 3
    conv3d_mma_kernel<<<dim3(256, 8), 256, CONV_SMEM>>>(grid_p, w1f, c1b, h1, CIN_,
        cnt_p, nullptr, nullptr, nullptr, nullptr, gs, gs2);                           // 4 <- ncu
    gn_finalize_kernel<<<1, B_ * NG_>>>(gs, gs2, mean_p, rstd_p, 16.0f * R3_);         // 5
    conv3d_mma_kernel<<<dim3(256, 8), 256, CONV_SMEM>>>(h1, w2f, c2b, h2, COUT_,
        nullptr, mean_p, rstd_p, g1g, g1b, gs, gs2);                                   // 6
    gn_finalize_kernel<<<1, B_ * NG_>>>(gs, gs2, mean2_p, rstd2_p, 16.0f * R3_);       // 7
    ptgemm_kernel<<<B_ * 64, 256, PT_SMEM>>>(features, ptwT, ptb, pf, gs, gs2);        // 8
    gn_finalize_kernel<<<1, B_ * NG_>>>(gs, gs2, mean_p, rstd_p, 16.0f * N_);          // 9
    final_kernel<<<4096, 256>>>(nc, h2, pf, g2g, g2b, mean2_p, rstd2_p,
                                pgg, pgb, mean_p, rstd_p, out);                        // 10
    cleanup_kernel<<<B_ * N_ / 256, 256>>>(vox_p, grid_p, cnt_p);                      // 11
}

// round 16
// speedup vs baseline: 1.8938x; 1.0537x over previous
#include <cuda_runtime.h>
#include <cuda_fp16.h>
#include <math.h>
#include <stdint.h>

#define B_    8
#define N_    4096
#define CIN_  64
#define COUT_ 128
#define R_    32
#define R3_   32768
#define NG_   8
#define GN_EPS_ 1e-5f

// ---------------- scratch (static device globals; no allocation) -------------
static __device__ float  g_grid[B_ * R3_ * CIN_];    // [b][voxel][ci]
static __device__ float  g_cnt [B_ * R3_];
static __device__ int    g_vox [B_ * N_];
static __device__ float  g_nc  [B_ * N_ * 3];
static __device__ __half g_h1  [B_ * COUT_ * R3_];   // fp16, channel-major
static __device__ __half g_h2  [B_ * R3_ * COUT_];   // fp16, channel-LAST
static __device__ float  g_pf  [B_ * COUT_ * N_];
static __device__ float  g_mean [B_ * NG_];
static __device__ float  g_rstd [B_ * NG_];
static __device__ float  g_mean2[B_ * NG_];
static __device__ float  g_rstd2[B_ * NG_];
static __device__ float  g_sum [B_ * NG_];
static __device__ float  g_sum2[B_ * NG_];
// W in mma A-fragment layout: [tap][chunk][cohalf][m 4][k 2][lane 32] x uint4
static __device__ uint4 g_w1f[27648];
static __device__ uint4 g_w2f[55296];
static __device__ float g_ptwT[CIN_ * COUT_];        // pt_w transposed [ci][co]

// ---------------- mma.sync m16n8k16 fp16 ------------------------------------
#define MMA_F16(dd, a0, a1, a2, a3, b0, b1) \
    asm volatile("mma.sync.aligned.m16n8k16.row.col.f32.f16.f16.f32 " \
        "{%0,%1,%2,%3}, {%4,%5,%6,%7}, {%8,%9}, {%0,%1,%2,%3};" \
        : "+f"((dd)[0]), "+f"((dd)[1]), "+f"((dd)[2]), "+f"((dd)[3]) \
        : "r"(a0), "r"(a1), "r"(a2), "r"(a3), "r"(b0), "r"(b1))

__device__ __forceinline__ void ldsm4(uint32_t* r, uint32_t addr) {
    asm volatile("ldmatrix.sync.aligned.m8n8.x4.shared.b16 {%0,%1,%2,%3}, [%4];"
        : "=r"(r[0]), "=r"(r[1]), "=r"(r[2]), "=r"(r[3]) : "r"(addr));
}
__device__ __forceinline__ uint32_t smem_u32(const void* p) {
    uint32_t a;
    asm("{ .reg .u64 t; cvta.to.shared.u64 t, %1; cvt.u32.u64 %0, t; }" : "=r"(a) : "l"(p));
    return a;
}
__device__ __forceinline__ float fast_swish(float y) {
    return y / (1.0f + __expf(-y));
}

// ============================ coords ==========================================
__global__ void coords_kernel(const float* __restrict__ coords,
                              float* __restrict__ nc, int* __restrict__ vox,
                              float* __restrict__ cnt) {
    int b = blockIdx.x, tid = threadIdx.x;
    __shared__ float red[256];
    __shared__ float smean[3];
    __shared__ float sinv;

    float s0 = 0.f, s1 = 0.f, s2 = 0.f;
    for (int n = tid; n < N_; n += 256) {
        const float* c = &coords[(b * N_ + n) * 3];
        s0 += c[0]; s1 += c[1]; s2 += c[2];
    }
    float ss[3] = {s0, s1, s2};
    for (int d = 0; d < 3; d++) {
        red[tid] = ss[d]; __syncthreads();
        for (int st = 128; st > 0; st >>= 1) {
            if (tid < st) red[tid] += red[tid + st];
            __syncthreads();
        }
        if (tid == 0) smean[d] = red[0] * (1.0f / N_);
        __syncthreads();
    }
    float m0 = smean[0], m1 = smean[1], m2 = smean[2];

    float mx = 0.f;
    for (int n = tid; n < N_; n += 256) {
        const float* c = &coords[(b * N_ + n) * 3];
        float dx = c[0] - m0, dy = c[1] - m1, dz = c[2] - m2;
        mx = fmaxf(mx, dx * dx + dy * dy + dz * dz);
    }
    red[tid] = mx; __syncthreads();
    for (int st = 128; st > 0; st >>= 1) {
        if (tid < st) red[tid] = fmaxf(red[tid], red[tid + st]);
        __syncthreads();
    }
    if (tid == 0) sinv = 1.0f / (2.0f * sqrtf(red[0]));
    __syncthreads();
    float inv = sinv;

    for (int n = tid; n < N_; n += 256) {
        const float* c = &coords[(b * N_ + n) * 3];
        float v[3]; int iv[3];
        float cc[3] = {c[0] - m0, c[1] - m1, c[2] - m2};
        #pragma unroll
        for (int d = 0; d < 3; d++) {
            float x = (cc[d] * inv + 0.5f) * (float)R_;
            x = fminf(fmaxf(x, 0.f), (float)(R_ - 1));
            v[d] = x;
            iv[d] = (int)rintf(x);
        }
        nc[(b * N_ + n) * 3 + 0] = v[0];
        nc[(b * N_ + n) * 3 + 1] = v[1];
        nc[(b * N_ + n) * 3 + 2] = v[2];
        int flat = (iv[0] * R_ + iv[1]) * R_ + iv[2];
        vox[b * N_ + n] = flat;
        atomicAdd(&cnt[b * R3_ + flat], 1.0f);
    }
}

// ---------------- weight prep: conv fragments + ptw transpose ----------------
__device__ __forceinline__ void wprep_one(const float* __restrict__ w, int Cin,
                                          uint4* __restrict__ of, int idx, int nch) {
    int lane = idx & 31;
    int blk = idx >> 5;
    int k = blk & 1;
    int m = (blk >> 1) & 3;
    int h = (blk >> 3) & 1;
    int ch = (blk >> 4) % nch;
    int tap = (blk >> 4) / nch;
    int g = lane >> 2, t4 = lane & 3;
    uint32_t regs[4];
    #pragma unroll
    for (int r = 0; r < 4; r++) {
        int co = h * 64 + m * 16 + g + (r & 1) * 8;
        int ci = ch * 32 + k * 16 + t4 * 2 + (r >> 1) * 8;
        __half2 hv = __floats2half2_rn(w[(co * Cin + ci) * 27 + tap],
                                       w[(co * Cin + ci + 1) * 27 + tap]);
        regs[r] = *(uint32_t*)&hv;
    }
    of[idx] = make_uint4(regs[0], regs[1], regs[2], regs[3]);
}

__global__ void wprep2_kernel(const float* __restrict__ w1, const float* __restrict__ w2,
                              const float* __restrict__ ptw,
                              uint4* __restrict__ o1, uint4* __restrict__ o2,
                              float* __restrict__ wT) {
    int t = blockIdx.x * 256 + threadIdx.x;
    if (t < 27648) wprep_one(w1, CIN_, o1, t, 2);
    else if (t < 27648 + 55296) wprep_one(w2, COUT_, o2, t - 27648, 4);
    else if (t < 27648 + 55296 + 8192) {
        int i = t - (27648 + 55296);
        int co = i >> 6, ci = i & 63;
        wT[ci * COUT_ + co] = ptw[co * CIN_ + ci];
    }
}

// ---------------- scatter (smem transpose -> coalesced atomics) --------------
__global__ void scatter_t_kernel(const float* __restrict__ f,
                                 const int* __restrict__ vox,
                                 float* __restrict__ grid) {
    int b = blockIdx.x >> 6, ng = blockIdx.x & 63;
    int n0 = ng * 64;
    int tid = threadIdx.x;
    __shared__ float buf[64][65];
    #pragma unroll
    for (int k = 0; k < 16; k++) {
        int idx = k * 256 + tid;
        int c = idx >> 6, dn = idx & 63;
        buf[c][dn] = f[((size_t)b * 64 + c) * N_ + n0 + dn];
    }
    __syncthreads();
    #pragma unroll
    for (int k = 0; k < 16; k++) {
        int idx = k * 256 + tid;
        int dn = idx >> 6, c = idx & 63;
        int flat = vox[b * N_ + n0 + dn];
        atomicAdd(&grid[((size_t)b * R3_ + flat) * 64 + c], buf[c][dn]);
    }
}

// ---------------- cleanup (end of run): zero occupied grid cols + cnt --------
__global__ void cleanup_kernel(const int* __restrict__ vox,
                               float* __restrict__ grid, float* __restrict__ cnt) {
    int t = blockIdx.x * 256 + threadIdx.x;   // B*N
    int b = t >> 12;
    int flat = vox[t];
    cnt[b * R3_ + flat] = 0.f;
    float4* g4 = (float4*)&grid[((size_t)b * R3_ + flat) * 64];
    const float4 z = make_float4(0.f, 0.f, 0.f, 0.f);
    #pragma unroll
    for (int k = 0; k < 16; k++) g4[k] = z;
}

// ---------------- GN + swish applied ONCE to h1 (fp16 in/out) ----------------
__global__ void gn_apply_h1_kernel(__half* __restrict__ x,
                                   const float* __restrict__ gamma,
                                   const float* __restrict__ beta,
                                   const float* __restrict__ mean,
                                   const float* __restrict__ rstd) {
    int t = blockIdx.x * 256 + threadIdx.x;      // over B*COUT*R3/8 uint4's
    int c = (t >> 12) & 127;                     // R3/8 = 4096 vecs per channel
    int b = t >> 19;                             // / (128*4096)
    int gi = b * NG_ + (c >> 4);
    float sc = rstd[gi] * gamma[c];
    float sh = beta[c] - mean[gi] * sc;
    uint4 raw = ((const uint4*)x)[t];
    uint32_t* rp = &raw.x;
    #pragma unroll
    for (int q = 0; q < 4; q++) {
        __half2 h2v = *(__half2*)&rp[q];
        float y0 = fast_swish(__low2float(h2v) * sc + sh);
        float y1 = fast_swish(__high2float(h2v) * sc + sh);
        __half2 o = __floats2half2_rn(y0, y1);
        rp[q] = *(uint32_t*)&o;
    }
    ((uint4*)x)[t] = raw;
}

// ============================ mma.sync conv3d (fp16) =========================
#define LSTRB   2720
#define FLG_OFF 43520
#define RC_OFF  43584
#define CONV_SMEM 45632

__global__ __launch_bounds__(256, 2)
void conv3d_mma_kernel(const void* __restrict__ in,
                       const uint4* __restrict__ wf,
                       const float* __restrict__ bias,
                       __half* __restrict__ out, int Cin,
                       const float* __restrict__ cnt,
                       float* __restrict__ gs, float* __restrict__ gs2) {
    extern __shared__ __align__(16) char smem[];
    __half* X = (__half*)smem;
    int* flags = (int*)(smem + FLG_OFF);
    float* rc = (float*)(smem + RC_OFF);
    uint32_t sb = smem_u32(smem);
    uint32_t x_u = sb;

    int tid = threadIdx.x, wid = tid >> 5, lane = tid & 31;
    int bx = blockIdx.x, b = blockIdx.y;
    int x0 = (bx >> 4) * 2, y0 = (bx & 15) * 2;
    int nch = Cin >> 5;
    int line = wid & 3;
    int cohalf = wid >> 2;
    int cobase = cohalf * 64;
    int g = lane >> 2, t4 = lane & 3;
    bool hc = (cnt != nullptr);

    uint32_t b_off = ((uint32_t)((lane & 7) + (lane >> 4) * 8) * 40
                      + (uint32_t)((lane >> 3) & 1) * 8) * 2;

    if (tid < 16) flags[tid] = hc ? 0 : 1;
    __syncthreads();
    if (hc) {
        for (int i = tid; i < 512; i += 256) {
            int il = i >> 5, z = i & 31;
            int gx = x0 - 1 + (il >> 2), gy = y0 - 1 + (il & 3);
            float c = 0.f;
            if ((unsigned)gx < 32u && (unsigned)gy < 32u)
                c = cnt[(size_t)b * R3_ + gx * 1024 + gy * 32 + z];
            rc[i] = __frcp_rn(fmaxf(c, 1.f));
            if (c > 0.f) flags[il] = 1;
        }
    }

    float d[4][4][4];
    #pragma unroll
    for (int m = 0; m < 4; m++)
        #pragma unroll
        for (int n = 0; n < 4; n++)
            #pragma unroll
            for (int r = 0; r < 4; r++) d[m][n][r] = 0.f;

    for (int ch = 0; ch < nch; ch++) {
        int c0 = ch * 32;
        __syncthreads();
        for (int i = tid; i < 1024; i += 256) {
            int ci = i & 31, r2 = (i >> 5) & 1, il = i >> 6;
            X[il * 1360 + (r2 ? 33 : 0) * 40 + ci] = __float2half_rn(0.f);
        }
        if (hc) {
            const float* inf = (const float*)in;
            for (int i = tid; i < 4096; i += 256) {
                int c4 = i & 7;
                int z  = (i >> 3) & 31;
                int il = i >> 8;
                int gx = x0 - 1 + (il >> 2), gy = y0 - 1 + (il & 3);
                float4 v = make_float4(0.f, 0.f, 0.f, 0.f);
                if ((unsigned)gx < 32u && (unsigned)gy < 32u)
                    v = *(const float4*)&inf[((size_t)b * R3_ + gx * 1024 + gy * 32 + z) * 64 + c0 + c4 * 4];
                float r = rc[il * 32 + z];
                int base = il * 1360 + (z + 1) * 40 + c4 * 4;
                *(__half2*)&X[base]     = __floats2half2_rn(v.x * r, v.y * r);
                *(__half2*)&X[base + 2] = __floats2half2_rn(v.z * r, v.w * r);
            }
        } else {
            // conv2: pure fp16 copy (GN+swish already applied to h1)
            const __half* inh = (const __half*)in;
            for (int i = tid; i < 2048; i += 256) {
                int zo = (i & 3) * 8;
                int ci = (i >> 2) & 31;
                int il = i >> 7;
                int gx = x0 - 1 + (il >> 2), gy = y0 - 1 + (il & 3);
                uint4 raw = make_uint4(0, 0, 0, 0);
                if ((unsigned)gx < 32u && (unsigned)gy < 32u)
                    raw = *(const uint4*)&inh[((size_t)(b * Cin + c0 + ci)) * R3_
                                              + gx * 1024 + gy * 32 + zo];
                const uint32_t* rp = &raw.x;
                int base = il * 1360 + (zo + 1) * 40 + ci;
                #pragma unroll
                for (int q = 0; q < 4; q++) {
                    __half2 h2v = *(__half2*)&rp[q];
                    X[base + (q * 2) * 40]     = __low2half(h2v);
                    X[base + (q * 2 + 1) * 40] = __high2half(h2v);
                }
            }
        }
        __syncthreads();

        // taps fully unrolled; A fragments batch-loaded per tap
        const uint4* wchunk = wf + ((size_t)ch * 2 + cohalf) * 8 * 32 + lane;
        const size_t tapstride = (size_t)nch * 2 * 8 * 32;
        #pragma unroll
        for (int dxx = 0; dxx < 3; dxx++) {
            #pragma unroll
            for (int dyy = 0; dyy < 3; dyy++) {
                int il = ((line >> 1) + dxx) * 4 + (line & 1) + dyy;
                int fl = flags[il];
                uint32_t xb0 = x_u + (uint32_t)il * LSTRB + b_off;
                const uint4* wt0 = wchunk + (size_t)(dxx * 9 + dyy * 3) * tapstride;
                #pragma unroll
                for (int dz = 0; dz < 3; dz++) {
                    if (fl) {
                        const uint4* wt = wt0 + (size_t)dz * tapstride;
                        uint4 A[8];
                        #pragma unroll
                        for (int mk = 0; mk < 8; mk++) A[mk] = wt[mk * 32];
                        uint32_t xb = xb0 + (uint32_t)dz * 80;
                        uint32_t Bf[2][8];
                        #pragma unroll
                        for (int k = 0; k < 2; k++) {
                            ldsm4(&Bf[k][0], xb + (uint32_t)k * 32);
                            ldsm4(&Bf[k][4], xb + 1280 + (uint32_t)k * 32);
                        }
                        #pragma unroll
                        for (int m = 0; m < 4; m++) {
                            #pragma unroll
                            for (int k = 0; k < 2; k++) {
                                const uint4& Av = A[m * 2 + k];
                                #pragma unroll
                                for (int n = 0; n < 4; n++)
                                    MMA_F16(d[m][n], Av.x, Av.y, Av.z, Av.w,
                                            Bf[k][n * 2], Bf[k][n * 2 + 1]);
                            }
                        }
                    }
                }
            }
        }
    }

    // ---------------- epilogue -------------------------------------------------
    if (hc) {
        int ox = x0 + (line >> 1), oy = y0 + (line & 1);
        #pragma unroll
        for (int m = 0; m < 4; m++) {
            int co = cobase + m * 16 + g;
            float bv0 = bias[co], bv1 = bias[co + 8];
            float s = 0.f, s2 = 0.f;
            __half* p0 = out + ((size_t)(b * COUT_ + co)) * R3_ + ox * 1024 + oy * 32;
            __half* p1 = p0 + (size_t)8 * R3_;
            #pragma unroll
            for (int n = 0; n < 4; n++) {
                float v0 = d[m][n][0] + bv0, v1 = d[m][n][1] + bv0;
                float v2 = d[m][n][2] + bv1, v3 = d[m][n][3] + bv1;
                int z = n * 8 + t4 * 2;
                *(__half2*)(p0 + z) = __floats2half2_rn(v0, v1);
                *(__half2*)(p1 + z) = __floats2half2_rn(v2, v3);
                s += v0 + v1 + v2 + v3;
                s2 += v0 * v0 + v1 * v1 + v2 * v2 + v3 * v3;
            }
            #pragma unroll
            for (int off = 16; off > 0; off >>= 1) {
                s += __shfl_xor_sync(0xffffffffu, s, off);
                s2 += __shfl_xor_sync(0xffffffffu, s2, off);
            }
            if (lane == 0) {
                int grp = b * NG_ + (cobase >> 4) + m;
                atomicAdd(&gs[grp], s);
                atomicAdd(&gs2[grp], s2);
            }
        }
    } else {
        __syncthreads();
        __half* T = (__half*)smem;       // [4 lines][32 z][128 co]
        #pragma unroll
        for (int m = 0; m < 4; m++) {
            int co = cobase + m * 16 + g;
            float bv0 = bias[co], bv1 = bias[co + 8];
            float s = 0.f, s2 = 0.f;
            #pragma unroll
            for (int n = 0; n < 4; n++) {
                float v0 = d[m][n][0] + bv0, v1 = d[m][n][1] + bv0;
                float v2 = d[m][n][2] + bv1, v3 = d[m][n][3] + bv1;
                int z = n * 8 + t4 * 2;
                __half* tb = T + (size_t)line * 4096;
                tb[(z) * 128 + co]     = __float2half_rn(v0);
                tb[(z + 1) * 128 + co] = __float2half_rn(v1);
                tb[(z) * 128 + co + 8]     = __float2half_rn(v2);
                tb[(z + 1) * 128 + co + 8] = __float2half_rn(v3);
                s += v0 + v1 + v2 + v3;
                s2 += v0 * v0 + v1 * v1 + v2 * v2 + v3 * v3;
            }
            #pragma unroll
            for (int off = 16; off > 0; off >>= 1) {
                s += __shfl_xor_sync(0xffffffffu, s, off);
                s2 += __shfl_xor_sync(0xffffffffu, s2, off);
            }
            if (lane == 0) {
                int grp = b * NG_ + (cobase >> 4) + m;
                atomicAdd(&gs[grp], s);
                atomicAdd(&gs2[grp], s2);
            }
        }
        __syncthreads();
        const uint4* Tv = (const uint4*)T;
        for (int i = tid; i < 2048; i += 256) {
            int l = i >> 9, j = i & 511;
            int ox = x0 + (l >> 1), oy = y0 + (l & 1);
            uint4* dst = (uint4*)(out + ((size_t)b * R3_ + ox * 1024 + oy * 32) * 128);
            dst[j] = Tv[i];
        }
    }
}

// ---------------- finalize GN stats (count-parameterized) ---------------------
__global__ void gn_finalize_kernel(float* __restrict__ gs, float* __restrict__ gs2,
                                   float* __restrict__ mean, float* __restrict__ rstd,
                                   float n) {
    int i = threadIdx.x;
    float s = gs[i], s2 = gs2[i];
    float m = s / n;
    mean[i] = m;
    rstd[i] = rsqrtf(s2 / n - m * m + GN_EPS_);
    gs[i] = 0.f; gs2[i] = 0.f;
}

// ---------------- tiled point GEMM + fused GN stats ---------------------------
#define PT_SMEM (64 * 64 * 4 + 64 * 129 * 4)
__global__ __launch_bounds__(256)
void ptgemm_kernel(const float* __restrict__ f, const float* __restrict__ wT,
                   const float* __restrict__ bias, float* __restrict__ pf,
                   float* __restrict__ gs, float* __restrict__ gs2) {
    extern __shared__ float ps[];
    float* sF = ps;              // [64][64]
    float* sW = ps + 4096;       // [64][129]
    int bidx = blockIdx.x;
    int b = bidx >> 6, n0 = (bidx & 63) * 64;
    int tid = threadIdx.x;

    for (int i = tid; i < 4096; i += 256) {
        int ci = i >> 6, n = i & 63;
        sF[ci * 64 + n] = f[((size_t)b * 64 + ci) * N_ + n0 + n];
    }
    for (int i = tid; i < 8192; i += 256) {
        int ci = i >> 7, co = i & 127;
        sW[ci * 129 + co] = wT[ci * COUT_ + co];
    }
    __syncthreads();

    int co = tid & 127, ng = tid >> 7;
    float acc[32];
    float bv = bias[co];
    #pragma unroll
    for (int j = 0; j < 32; j++) acc[j] = bv;
    for (int ci = 0; ci < 64; ci++) {
        float wv = sW[ci * 129 + co];
        const float* fr = sF + ci * 64 + ng * 32;
        #pragma unroll
        for (int j = 0; j < 32; j++) acc[j] += wv * fr[j];
    }
    float* op = &pf[((size_t)b * COUT_ + co) * N_ + n0 + ng * 32];
    float s = 0.f, s2 = 0.f;
    #pragma unroll
    for (int j = 0; j < 32; j++) {
        op[j] = acc[j];
        s += acc[j]; s2 += acc[j] * acc[j];
    }
    #pragma unroll
    for (int off = 8; off > 0; off >>= 1) {
        s += __shfl_down_sync(0xffffffffu, s, off);
        s2 += __shfl_down_sync(0xffffffffu, s2, off);
    }
    if ((tid & 15) == 0) {
        int grp = b * NG_ + (co >> 4);
        atomicAdd(&gs[grp], s);
        atomicAdd(&gs2[grp], s2);
    }
}

// -------- devoxelize (fp16 channel-last h2, fused GN+swish) + point branch ---
__global__ void final_kernel(const float* __restrict__ nc, const __half* __restrict__ h2,
                             const float* __restrict__ pf,
                             const float* __restrict__ g2g, const float* __restrict__ g2b,
                             const float* __restrict__ mean2, const float* __restrict__ rstd2,
                             const float* __restrict__ pgg, const float* __restrict__ pgb,
                             const float* __restrict__ meanp, const float* __restrict__ rstdp,
                             float* __restrict__ out) {
    int t = blockIdx.x * blockDim.x + threadIdx.x;
    int n = t & (N_ - 1);
    int r = t >> 12;
    int o = (r & 31) * 4;
    int b = r >> 5;

    float ncx = nc[(b * N_ + n) * 3 + 0];
    float ncy = nc[(b * N_ + n) * 3 + 1];
    float ncz = nc[(b * N_ + n) * 3 + 2];
    float fx = floorf(ncx), fy = floorf(ncy), fz = floorf(ncz);
    float dx = ncx - fx, dy = ncy - fy, dz = ncz - fz;
    int ix0 = (int)fx, iy0 = (int)fy, iz0 = (int)fz;
    int ix1 = min(ix0 + 1, R_ - 1), iy1 = min(iy0 + 1, R_ - 1), iz1 = min(iz0 + 1, R_ - 1);
    float wx[2] = {1.f - dx, dx}, wy[2] = {1.f - dy, dy}, wz[2] = {1.f - dz, dz};
    int xs[2] = {ix0, ix1}, ys[2] = {iy0, iy1}, zs[2] = {iz0, iz1};

    int gidx = b * NG_ + (o >> 4);
    float m2 = mean2[gidx], rs2 = rstd2[gidx];
    float ga[4], be[4];
    #pragma unroll
    for (int j = 0; j < 4; j++) { ga[j] = g2g[o + j]; be[j] = g2b[o + j]; }

    float dv[4] = {0.f, 0.f, 0.f, 0.f};
    const __half* hb = h2 + ((size_t)b * R3_) * 128;
    #pragma unroll
    for (int k = 0; k < 8; k++) {
        int kx = k >> 2, ky = (k >> 1) & 1, kz = k & 1;
        float wk = wx[kx] * wy[ky] * wz[kz];
        int id = (xs[kx] * R_ + ys[ky]) * R_ + zs[kz];
        uint2 raw = *(const uint2*)&hb[(size_t)id * 128 + o];
        __half2 a01 = *(__half2*)&raw.x, a23 = *(__half2*)&raw.y;
        float hv[4] = {__low2float(a01), __high2float(a01),
                       __low2float(a23), __high2float(a23)};
        #pragma unroll
        for (int j = 0; j < 4; j++) {
            float y = (hv[j] - m2) * rs2 * ga[j] + be[j];
            dv[j] += wk * fast_swish(y);
        }
    }

    float mp = meanp[gidx], rsp = rstdp[gidx];
    const float* pp = &pf[(b * COUT_ + o) * N_ + n];
    float* op = &out[(b * COUT_ + o) * N_ + n];
    #pragma unroll
    for (int j = 0; j < 4; j++) {
        int c = o + j;
        float y = (pp[j * N_] - mp) * rsp * pgg[c] + pgb[c];
        op[j * N_] = dv[j] + fast_swish(y);
    }
}

// ---------------- host launcher ----------------------------------------------
extern "C" void kernel_launch(void* const* d_in, const int* in_sizes, int n_in,
                              void* d_out, int out_size) {
    const float* features = (const float*)d_in[0];
    const float* coords   = (const float*)d_in[1];
    const float* c1w = (const float*)d_in[2];
    const float* c1b = (const float*)d_in[3];
    const float* g1g = (const float*)d_in[4];
    const float* g1b = (const float*)d_in[5];
    const float* c2w = (const float*)d_in[6];
    const float* c2b = (const float*)d_in[7];
    const float* g2g = (const float*)d_in[8];
    const float* g2b = (const float*)d_in[9];
    const float* ptw = (const float*)d_in[10];
    const float* ptb = (const float*)d_in[11];
    const float* pgg = (const float*)d_in[12];
    const float* pgb = (const float*)d_in[13];
    float* out = (float*)d_out;

    float *grid_p, *cnt_p, *pf, *nc, *ptwT;
    float *mean_p, *rstd_p, *mean2_p, *rstd2_p, *gs, *gs2;
    __half *h1, *h2;
    int* vox_p;
    uint4 *w1f, *w2f;
    cudaGetSymbolAddress((void**)&grid_p, g_grid);
    cudaGetSymbolAddress((void**)&cnt_p, g_cnt);
    cudaGetSymbolAddress((void**)&vox_p, g_vox);
    cudaGetSymbolAddress((void**)&nc, g_nc);
    cudaGetSymbolAddress((void**)&h1, g_h1);
    cudaGetSymbolAddress((void**)&h2, g_h2);
    cudaGetSymbolAddress((void**)&pf, g_pf);
    cudaGetSymbolAddress((void**)&mean_p, g_mean);
    cudaGetSymbolAddress((void**)&rstd_p, g_rstd);
    cudaGetSymbolAddress((void**)&mean2_p, g_mean2);
    cudaGetSymbolAddress((void**)&rstd2_p, g_rstd2);
    cudaGetSymbolAddress((void**)&gs, g_sum);
    cudaGetSymbolAddress((void**)&gs2, g_sum2);
    cudaGetSymbolAddress((void**)&w1f, g_w1f);
    cudaGetSymbolAddress((void**)&w2f, g_w2f);
    cudaGetSymbolAddress((void**)&ptwT, g_ptwT);

    cudaFuncSetAttribute(conv3d_mma_kernel,
                         cudaFuncAttributeMaxDynamicSharedMemorySize, CONV_SMEM);
    cudaFuncSetAttribute(ptgemm_kernel,
                         cudaFuncAttributeMaxDynamicSharedMemorySize, PT_SMEM);

    coords_kernel<<<B_, 256>>>(coords, nc, vox_p, cnt_p);                              // 1
    wprep2_kernel<<<(27648 + 55296 + 8192 + 255) / 256, 256>>>(c1w, c2w, ptw,
                                                               w1f, w2f, ptwT);        // 2
    scatter_t_kernel<<<B_ * 64, 256>>>(features, vox_p, grid_p);                       // 3
    conv3d_mma_kernel<<<dim3(256, 8), 256, CONV_SMEM>>>(grid_p, w1f, c1b, h1, CIN_,
                                                        cnt_p, gs, gs2);               // 4 <- ncu
    gn_finalize_kernel<<<1, B_ * NG_>>>(gs, gs2, mean_p, rstd_p, 16.0f * R3_);         // 5
    gn_apply_h1_kernel<<<16384, 256>>>(h1, g1g, g1b, mean_p, rstd_p);                  // 6
    conv3d_mma_kernel<<<dim3(256, 8), 256, CONV_SMEM>>>(h1, w2f, c2b, h2, COUT_,
                                                        nullptr, gs, gs2);             // 7
    gn_finalize_kernel<<<1, B_ * NG_>>>(gs, gs2, mean2_p, rstd2_p, 16.0f * R3_);       // 8
    ptgemm_kernel<<<B_ * 64, 256, PT_SMEM>>>(features, ptwT, ptb, pf, gs, gs2);        // 9
    gn_finalize_kernel<<<1, B_ * NG_>>>(gs, gs2, mean_p, rstd_p, 16.0f * N_);          // 10
    final_kernel<<<4096, 256>>>(nc, h2, pf, g2g, g2b, mean2_p, rstd2_p,
                                pgg, pgb, mean_p, rstd_p, out);                        // 11
    cleanup_kernel<<<B_ * N_ / 256, 256>>>(vox_p, grid_p, cnt_p);                      // 12
}